// round 1
// baseline (speedup 1.0000x reference)
#include <cuda_runtime.h>
#include <math.h>

// Problem constants
#define D_MODEL 2048
#define SEQ     2048
#define BATCH   2
#define NHEAD   16
#define KVHEAD  4
#define HDIM    128
#define FF      5632
#define MTOT    (BATCH * SEQ)      // 4096 rows
#define KD      (KVHEAD * HDIM)    // 512

// ---------------------------------------------------------------------------
// Scratch buffers (no cudaMalloc allowed)
// ---------------------------------------------------------------------------
__device__ float g_h  [MTOT * (size_t)D_MODEL];  // rmsnorm out, then attn out
__device__ float g_q  [MTOT * (size_t)D_MODEL];  // q proj, then h2 (rmsnorm2)
__device__ float g_k  [MTOT * (size_t)KD];
__device__ float g_v  [MTOT * (size_t)KD];
__device__ float g_act[MTOT * (size_t)FF];       // gate, then silu(gate)*up

// ---------------------------------------------------------------------------
// RMSNorm: one block per row (D=2048, 256 threads, 8 floats/thread)
// ---------------------------------------------------------------------------
__global__ void __launch_bounds__(256) rmsnorm_kernel(
    const float* __restrict__ x, const float* __restrict__ w,
    float* __restrict__ o)
{
    const int row = blockIdx.x;
    const float* xr = x + (size_t)row * D_MODEL;
    float* orow     = o + (size_t)row * D_MODEL;
    const int t = threadIdx.x;

    float4 a = *(const float4*)(xr + t * 4);
    float4 b = *(const float4*)(xr + 1024 + t * 4);
    float ss = a.x*a.x + a.y*a.y + a.z*a.z + a.w*a.w
             + b.x*b.x + b.y*b.y + b.z*b.z + b.w*b.w;

    #pragma unroll
    for (int off = 16; off; off >>= 1)
        ss += __shfl_xor_sync(0xffffffffu, ss, off);

    __shared__ float warp_s[8];
    if ((t & 31) == 0) warp_s[t >> 5] = ss;
    __syncthreads();
    float tot = 0.f;
    #pragma unroll
    for (int i = 0; i < 8; ++i) tot += warp_s[i];

    const float inv = rsqrtf(tot * (1.0f / D_MODEL) + 1e-6f);

    float4 w1 = *(const float4*)(w + t * 4);
    float4 w2 = *(const float4*)(w + 1024 + t * 4);
    float4 o1, o2;
    o1.x = a.x * inv * w1.x; o1.y = a.y * inv * w1.y;
    o1.z = a.z * inv * w1.z; o1.w = a.w * inv * w1.w;
    o2.x = b.x * inv * w2.x; o2.y = b.y * inv * w2.y;
    o2.z = b.z * inv * w2.z; o2.w = b.w * inv * w2.w;
    *(float4*)(orow + t * 4)        = o1;
    *(float4*)(orow + 1024 + t * 4) = o2;
}

// ---------------------------------------------------------------------------
// SGEMM: C[M,N] = A[M,K] @ W[N,K]^T  (+ epilogue)
//   EPI 0: + bias[col]   (aux = bias vector, may be null)
//   EPI 1: + aux[row,col] (residual matrix)
//   EPI 2: silu(aux[row,col]) * acc   (fused SwiGLU combine)
// Tile 128x128x16, 256 threads, 8x8 per thread. All dims assumed divisible.
// ---------------------------------------------------------------------------
template<int EPI>
__global__ void __launch_bounds__(256) sgemm_kernel(
    const float* __restrict__ A, const float* __restrict__ W,
    const float* aux, float* __restrict__ C,
    int M, int N, int K)
{
    __shared__ float As[16][128];
    __shared__ float Ws[16][128];

    const int tid = threadIdx.x;
    const int bm = blockIdx.y * 128;
    const int bn = blockIdx.x * 128;
    const int tx = tid & 15;
    const int ty = tid >> 4;
    const int lr = tid >> 2;          // 0..63
    const int lc = (tid & 3) << 2;    // 0,4,8,12

    float acc[8][8];
    #pragma unroll
    for (int i = 0; i < 8; ++i)
        #pragma unroll
        for (int j = 0; j < 8; ++j) acc[i][j] = 0.f;

    const float* Ab = A + (size_t)bm * K;
    const float* Wb = W + (size_t)bn * K;

    for (int kt = 0; kt < K; kt += 16) {
        #pragma unroll
        for (int s = 0; s < 2; ++s) {
            const int row = lr + s * 64;
            float4 av = *(const float4*)(Ab + (size_t)row * K + kt + lc);
            As[lc + 0][row] = av.x; As[lc + 1][row] = av.y;
            As[lc + 2][row] = av.z; As[lc + 3][row] = av.w;
            float4 wv = *(const float4*)(Wb + (size_t)row * K + kt + lc);
            Ws[lc + 0][row] = wv.x; Ws[lc + 1][row] = wv.y;
            Ws[lc + 2][row] = wv.z; Ws[lc + 3][row] = wv.w;
        }
        __syncthreads();

        #pragma unroll
        for (int k = 0; k < 16; ++k) {
            float a[8], b[8];
            *(float4*)(a)     = *(const float4*)&As[k][ty * 8];
            *(float4*)(a + 4) = *(const float4*)&As[k][ty * 8 + 4];
            *(float4*)(b)     = *(const float4*)&Ws[k][tx * 8];
            *(float4*)(b + 4) = *(const float4*)&Ws[k][tx * 8 + 4];
            #pragma unroll
            for (int i = 0; i < 8; ++i)
                #pragma unroll
                for (int j = 0; j < 8; ++j)
                    acc[i][j] += a[i] * b[j];
        }
        __syncthreads();
    }

    #pragma unroll
    for (int i = 0; i < 8; ++i) {
        const int row = bm + ty * 8 + i;
        #pragma unroll
        for (int jj = 0; jj < 2; ++jj) {
            const int col = bn + tx * 8 + jj * 4;
            const size_t idx = (size_t)row * N + col;
            float vals[4];
            #pragma unroll
            for (int j = 0; j < 4; ++j) {
                float v = acc[i][jj * 4 + j];
                if (EPI == 0) {
                    if (aux) v += aux[col + j];
                } else if (EPI == 1) {
                    v += aux[idx + j];
                } else { // EPI == 2: silu(gate) * acc
                    const float g = aux[idx + j];
                    v *= g / (1.0f + __expf(-g));
                }
                vals[j] = v;
            }
            float4 r; r.x = vals[0]; r.y = vals[1]; r.z = vals[2]; r.w = vals[3];
            *(float4*)(C + idx) = r;
        }
    }
}

// ---------------------------------------------------------------------------
// Flash attention (fp32, causal, GQA h -> h % KVH)
// Grid: (SEQ/64, NHEAD, BATCH), 256 threads.
// Each warp owns 8 q-rows; each lane owns 4 head-dim columns of O and
// 2 score columns of the 64-wide S tile.
// ---------------------------------------------------------------------------
#define QT 64
#define KT 64
#define SSTRIDE 132   // padded smem row stride for Q/K/V (float4 aligned)
#define PSTRIDE 65

__global__ void __launch_bounds__(256) flash_kernel(
    const float* __restrict__ Qb, const float* __restrict__ Kb,
    const float* __restrict__ Vb, float* __restrict__ Ob)
{
    extern __shared__ float sm[];
    float* Qs = sm;                      // 64*132
    float* Ks = Qs + QT * SSTRIDE;       // 64*132
    float* Vs = Ks + KT * SSTRIDE;       // 64*132
    float* Ps = Vs + KT * SSTRIDE;       // 64*65

    const int qt   = blockIdx.x;
    const int hh   = blockIdx.y;
    const int b    = blockIdx.z;
    const int g    = hh & (KVHEAD - 1);
    const int tid  = threadIdx.x;
    const int warp = tid >> 5;
    const int lane = tid & 31;
    const int r0   = warp * 8;
    const int qbase = qt * QT;

    // Load Q tile [64 x 128]
    const float* qptr = Qb + ((size_t)b * SEQ + qbase) * D_MODEL + hh * HDIM;
    #pragma unroll
    for (int it = 0; it < 8; ++it) {
        const int idx = tid + it * 256;
        const int row = idx >> 5;
        const int c4  = (idx & 31) << 2;
        float4 v = *(const float4*)(qptr + (size_t)row * D_MODEL + c4);
        float* d = &Qs[row * SSTRIDE + c4];
        d[0] = v.x; d[1] = v.y; d[2] = v.z; d[3] = v.w;
    }

    float acc[8][4];
    float m_i[8], l_i[8];
    #pragma unroll
    for (int i = 0; i < 8; ++i) {
        m_i[i] = -1e30f; l_i[i] = 0.f;
        acc[i][0] = acc[i][1] = acc[i][2] = acc[i][3] = 0.f;
    }
    const float scale = 0.08838834764831845f;  // 1/sqrt(128)
    const int c0 = lane * 2, c1 = c0 + 1;

    for (int kt = 0; kt <= qt; ++kt) {
        __syncthreads();  // previous iteration's consumers done; Q visible (iter 0)
        const float* kptr = Kb + ((size_t)b * SEQ + kt * KT) * KD + g * HDIM;
        const float* vptr = Vb + ((size_t)b * SEQ + kt * KT) * KD + g * HDIM;
        #pragma unroll
        for (int it = 0; it < 8; ++it) {
            const int idx = tid + it * 256;
            const int row = idx >> 5;
            const int c4  = (idx & 31) << 2;
            float4 kv = *(const float4*)(kptr + (size_t)row * KD + c4);
            float* dk = &Ks[row * SSTRIDE + c4];
            dk[0] = kv.x; dk[1] = kv.y; dk[2] = kv.z; dk[3] = kv.w;
            float4 vv = *(const float4*)(vptr + (size_t)row * KD + c4);
            float* dv = &Vs[row * SSTRIDE + c4];
            dv[0] = vv.x; dv[1] = vv.y; dv[2] = vv.z; dv[3] = vv.w;
        }
        __syncthreads();

        // S = Q K^T for this tile: thread computes rows r0..r0+7, cols c0,c1
        float s0[8], s1[8];
        #pragma unroll
        for (int i = 0; i < 8; ++i) { s0[i] = 0.f; s1[i] = 0.f; }
        #pragma unroll 8
        for (int kk = 0; kk < HDIM; kk += 4) {
            const float4 k0 = *(const float4*)&Ks[c0 * SSTRIDE + kk];
            const float4 k1 = *(const float4*)&Ks[c1 * SSTRIDE + kk];
            #pragma unroll
            for (int i = 0; i < 8; ++i) {
                const float4 q4 = *(const float4*)&Qs[(r0 + i) * SSTRIDE + kk];
                s0[i] += q4.x * k0.x + q4.y * k0.y + q4.z * k0.z + q4.w * k0.w;
                s1[i] += q4.x * k1.x + q4.y * k1.y + q4.z * k1.z + q4.w * k1.w;
            }
        }

        // Online softmax per row (warp-local reductions)
        #pragma unroll
        for (int i = 0; i < 8; ++i) {
            const int qi  = qbase + r0 + i;
            const int k0i = kt * KT + c0;
            const int k1i = k0i + 1;
            float v0 = s0[i] * scale;
            float v1 = s1[i] * scale;
            if (k0i > qi) v0 = -1e30f;
            if (k1i > qi) v1 = -1e30f;
            float mx = fmaxf(v0, v1);
            #pragma unroll
            for (int off = 16; off; off >>= 1)
                mx = fmaxf(mx, __shfl_xor_sync(0xffffffffu, mx, off));
            const float mnew = fmaxf(m_i[i], mx);
            const float p0 = __expf(v0 - mnew);
            const float p1 = __expf(v1 - mnew);
            float ps = p0 + p1;
            #pragma unroll
            for (int off = 16; off; off >>= 1)
                ps += __shfl_xor_sync(0xffffffffu, ps, off);
            const float alpha = __expf(m_i[i] - mnew);
            l_i[i] = l_i[i] * alpha + ps;
            m_i[i] = mnew;
            acc[i][0] *= alpha; acc[i][1] *= alpha;
            acc[i][2] *= alpha; acc[i][3] *= alpha;
            Ps[(r0 + i) * PSTRIDE + c0] = p0;
            Ps[(r0 + i) * PSTRIDE + c1] = p1;
        }
        __syncwarp();   // Ps is warp-private rows: warp-level ordering suffices

        // O += P @ V : each lane owns cols lane*4..+3
        #pragma unroll 4
        for (int k = 0; k < KT; ++k) {
            const float4 vv = *(const float4*)&Vs[k * SSTRIDE + lane * 4];
            #pragma unroll
            for (int i = 0; i < 8; ++i) {
                const float p = Ps[(r0 + i) * PSTRIDE + k];
                acc[i][0] += p * vv.x; acc[i][1] += p * vv.y;
                acc[i][2] += p * vv.z; acc[i][3] += p * vv.w;
            }
        }
    }

    // Write O (normalized)
    float* optr = Ob + ((size_t)b * SEQ + qbase) * D_MODEL + hh * HDIM;
    #pragma unroll
    for (int i = 0; i < 8; ++i) {
        const float inv = 1.0f / l_i[i];
        float4 o;
        o.x = acc[i][0] * inv; o.y = acc[i][1] * inv;
        o.z = acc[i][2] * inv; o.w = acc[i][3] * inv;
        *(float4*)(optr + (size_t)(r0 + i) * D_MODEL + lane * 4) = o;
    }
}

// ---------------------------------------------------------------------------
// Launch sequence
// ---------------------------------------------------------------------------
extern "C" void kernel_launch(void* const* d_in, const int* in_sizes, int n_in,
                              void* d_out, int out_size)
{
    const float* x      = (const float*)d_in[0];
    const float* ln1_w  = (const float*)d_in[1];
    const float* q_w    = (const float*)d_in[2];
    const float* q_b    = (const float*)d_in[3];
    const float* k_w    = (const float*)d_in[4];
    const float* k_b    = (const float*)d_in[5];
    const float* v_w    = (const float*)d_in[6];
    const float* v_b    = (const float*)d_in[7];
    const float* o_w    = (const float*)d_in[8];
    const float* ln2_w  = (const float*)d_in[9];
    const float* gate_w = (const float*)d_in[10];
    const float* up_w   = (const float*)d_in[11];
    const float* down_w = (const float*)d_in[12];
    float* out = (float*)d_out;

    float *h, *q, *k, *v, *act;
    cudaGetSymbolAddress((void**)&h,   g_h);
    cudaGetSymbolAddress((void**)&q,   g_q);
    cudaGetSymbolAddress((void**)&k,   g_k);
    cudaGetSymbolAddress((void**)&v,   g_v);
    cudaGetSymbolAddress((void**)&act, g_act);

    const int smem = (3 * QT * SSTRIDE + QT * PSTRIDE) * (int)sizeof(float);
    cudaFuncSetAttribute(flash_kernel,
                         cudaFuncAttributeMaxDynamicSharedMemorySize, smem);

    // 1. h = rmsnorm(x, ln1_w)
    rmsnorm_kernel<<<MTOT, 256>>>(x, ln1_w, h);

    // 2-4. q/k/v projections (+bias)
    sgemm_kernel<0><<<dim3(D_MODEL / 128, MTOT / 128), 256>>>(h, q_w, q_b, q, MTOT, D_MODEL, D_MODEL);
    sgemm_kernel<0><<<dim3(KD / 128,      MTOT / 128), 256>>>(h, k_w, k_b, k, MTOT, KD, D_MODEL);
    sgemm_kernel<0><<<dim3(KD / 128,      MTOT / 128), 256>>>(h, v_w, v_b, v, MTOT, KD, D_MODEL);

    // 5. flash attention -> reuse h as attention output
    flash_kernel<<<dim3(SEQ / QT, NHEAD, BATCH), 256, smem>>>(q, k, v, h);

    // 6. x1 = x + attn @ o_w^T   (into d_out)
    sgemm_kernel<1><<<dim3(D_MODEL / 128, MTOT / 128), 256>>>(h, o_w, x, out, MTOT, D_MODEL, D_MODEL);

    // 7. h2 = rmsnorm(x1, ln2_w) -> reuse q
    rmsnorm_kernel<<<MTOT, 256>>>(out, ln2_w, q);

    // 8. gate = h2 @ gate_w^T
    sgemm_kernel<0><<<dim3(FF / 128, MTOT / 128), 256>>>(q, gate_w, (const float*)nullptr, act, MTOT, FF, D_MODEL);

    // 9. act = silu(gate) * (h2 @ up_w^T)   (in place over gate buffer)
    sgemm_kernel<2><<<dim3(FF / 128, MTOT / 128), 256>>>(q, up_w, act, act, MTOT, FF, D_MODEL);

    // 10. out = x1 + act @ down_w^T   (residual read + write both in d_out)
    sgemm_kernel<1><<<dim3(D_MODEL / 128, MTOT / 128), 256>>>(act, down_w, out, out, MTOT, D_MODEL, FF);
}

// round 2
// speedup vs baseline: 1.9102x; 1.9102x over previous
#include <cuda_runtime.h>
#include <math.h>
#include <stdint.h>

// Problem constants
#define D_MODEL 2048
#define SEQ     2048
#define BATCH   2
#define NHEAD   16
#define KVHEAD  4
#define HDIM    128
#define FF      5632
#define MTOT    (BATCH * SEQ)      // 4096 rows
#define KD      (KVHEAD * HDIM)    // 512

// ---------------------------------------------------------------------------
// Scratch buffers (no cudaMalloc allowed)
// ---------------------------------------------------------------------------
__device__ float g_h  [MTOT * (size_t)D_MODEL];  // rmsnorm out, then attn out
__device__ float g_q  [MTOT * (size_t)D_MODEL];  // q proj, then h2 (rmsnorm2)
__device__ float g_k  [MTOT * (size_t)KD];
__device__ float g_v  [MTOT * (size_t)KD];
__device__ float g_act[MTOT * (size_t)FF];       // gate, then silu(gate)*up

// ---------------------------------------------------------------------------
// RMSNorm: one block per row (D=2048, 256 threads, 8 floats/thread)
// ---------------------------------------------------------------------------
__global__ void __launch_bounds__(256) rmsnorm_kernel(
    const float* __restrict__ x, const float* __restrict__ w,
    float* __restrict__ o)
{
    const int row = blockIdx.x;
    const float* xr = x + (size_t)row * D_MODEL;
    float* orow     = o + (size_t)row * D_MODEL;
    const int t = threadIdx.x;

    float4 a = *(const float4*)(xr + t * 4);
    float4 b = *(const float4*)(xr + 1024 + t * 4);
    float ss = a.x*a.x + a.y*a.y + a.z*a.z + a.w*a.w
             + b.x*b.x + b.y*b.y + b.z*b.z + b.w*b.w;

    #pragma unroll
    for (int off = 16; off; off >>= 1)
        ss += __shfl_xor_sync(0xffffffffu, ss, off);

    __shared__ float warp_s[8];
    if ((t & 31) == 0) warp_s[t >> 5] = ss;
    __syncthreads();
    float tot = 0.f;
    #pragma unroll
    for (int i = 0; i < 8; ++i) tot += warp_s[i];

    const float inv = rsqrtf(tot * (1.0f / D_MODEL) + 1e-6f);

    float4 w1 = *(const float4*)(w + t * 4);
    float4 w2 = *(const float4*)(w + 1024 + t * 4);
    float4 o1, o2;
    o1.x = a.x * inv * w1.x; o1.y = a.y * inv * w1.y;
    o1.z = a.z * inv * w1.z; o1.w = a.w * inv * w1.w;
    o2.x = b.x * inv * w2.x; o2.y = b.y * inv * w2.y;
    o2.z = b.z * inv * w2.z; o2.w = b.w * inv * w2.w;
    *(float4*)(orow + t * 4)        = o1;
    *(float4*)(orow + 1024 + t * 4) = o2;
}

// ---------------------------------------------------------------------------
// TF32 tensor-core GEMM: C[M,N] = A[M,K] @ W[N,K]^T (+ epilogue)
//   EPI 0: + bias[col]    (aux = bias vector, may be null)
//   EPI 1: + aux[row,col] (residual matrix)
//   EPI 2: silu(aux[row,col]) * acc  (fused SwiGLU combine)
// Block tile 128x128x32, 256 threads (8 warps, 2x4), warp tile 64x32.
// mma.sync.aligned.m16n8k8.row.col.f32.tf32.tf32.f32
// Smem stride 36 floats -> conflict-free fragment loads and float4 stores.
// ---------------------------------------------------------------------------
#define BM 128
#define BN 128
#define BK 32
#define SST 36                       // smem row stride (floats)
#define TILE_U (BM * SST)            // uints per tile buffer
#define GEMM_SMEM (4 * TILE_U * 4)   // 2 bufs * (A + B) * 4 bytes = 73728

__device__ __forceinline__ uint32_t f2tf32(float x) {
    uint32_t u;
    asm("cvt.rna.tf32.f32 %0, %1;" : "=r"(u) : "f"(x));
    return u;
}

#define MMA_TF32(d, a, b)                                                   \
    asm volatile(                                                           \
        "mma.sync.aligned.m16n8k8.row.col.f32.tf32.tf32.f32 "               \
        "{%0,%1,%2,%3}, {%4,%5,%6,%7}, {%8,%9}, {%0,%1,%2,%3};"             \
        : "+f"(d[0]), "+f"(d[1]), "+f"(d[2]), "+f"(d[3])                    \
        : "r"(a[0]), "r"(a[1]), "r"(a[2]), "r"(a[3]), "r"(b[0]), "r"(b[1]))

template<int EPI>
__global__ void __launch_bounds__(256) sgemm_tf32_kernel(
    const float* __restrict__ A, const float* __restrict__ W,
    const float* aux, float* __restrict__ C,
    int M, int N, int K)
{
    extern __shared__ uint32_t smem_u[];
    uint32_t* Abuf[2] = { smem_u,              smem_u + 2 * TILE_U };
    uint32_t* Bbuf[2] = { smem_u + TILE_U,     smem_u + 3 * TILE_U };

    const int tid  = threadIdx.x;
    const int warp = tid >> 5;
    const int lane = tid & 31;
    const int bm = blockIdx.y * BM;
    const int bn = blockIdx.x * BN;
    const int m_w = (warp >> 2) * 64;   // warp row base within tile (0/64)
    const int n_w = (warp & 3) * 32;    // warp col base within tile (0..96)
    const int lr4 = lane >> 2;          // 0..7
    const int lk  = lane & 3;           // 0..3

    const float* Ab = A + (size_t)bm * K;
    const float* Wb = W + (size_t)bn * K;

    // ld indices: idx = tid + i*256; row = idx>>3; col4 = (idx&7)*4
    float4 ar[4], br[4];

    float acc[4][4][4];
    #pragma unroll
    for (int mt = 0; mt < 4; ++mt)
        #pragma unroll
        for (int nt = 0; nt < 4; ++nt)
            #pragma unroll
            for (int r = 0; r < 4; ++r) acc[mt][nt][r] = 0.f;

    // ---- prologue: load tile 0 ----
    #pragma unroll
    for (int i = 0; i < 4; ++i) {
        const int idx = tid + i * 256;
        const int row = idx >> 3;
        const int c4  = (idx & 7) << 2;
        ar[i] = *(const float4*)(Ab + (size_t)row * K + c4);
        br[i] = *(const float4*)(Wb + (size_t)row * K + c4);
    }
    #pragma unroll
    for (int i = 0; i < 4; ++i) {
        const int idx = tid + i * 256;
        const int row = idx >> 3;
        const int c4  = (idx & 7) << 2;
        uint4 ua = { f2tf32(ar[i].x), f2tf32(ar[i].y), f2tf32(ar[i].z), f2tf32(ar[i].w) };
        uint4 ub = { f2tf32(br[i].x), f2tf32(br[i].y), f2tf32(br[i].z), f2tf32(br[i].w) };
        *(uint4*)&Abuf[0][row * SST + c4] = ua;
        *(uint4*)&Bbuf[0][row * SST + c4] = ub;
    }
    __syncthreads();

    const int nk = K / BK;
    int cur = 0;
    for (int kt = 0; kt < nk; ++kt) {
        // issue next tile's global loads early
        if (kt + 1 < nk) {
            const int k0 = (kt + 1) * BK;
            #pragma unroll
            for (int i = 0; i < 4; ++i) {
                const int idx = tid + i * 256;
                const int row = idx >> 3;
                const int c4  = (idx & 7) << 2;
                ar[i] = *(const float4*)(Ab + (size_t)row * K + k0 + c4);
                br[i] = *(const float4*)(Wb + (size_t)row * K + k0 + c4);
            }
        }

        // compute on buffer `cur`
        const uint32_t* As = Abuf[cur];
        const uint32_t* Bs = Bbuf[cur];
        #pragma unroll
        for (int kk = 0; kk < 4; ++kk) {
            const int k0 = kk * 8;
            uint32_t afr[4][4], bfr[4][2];
            #pragma unroll
            for (int mt = 0; mt < 4; ++mt) {
                const int r = m_w + mt * 16 + lr4;
                afr[mt][0] = As[r * SST + k0 + lk];
                afr[mt][1] = As[(r + 8) * SST + k0 + lk];
                afr[mt][2] = As[r * SST + k0 + lk + 4];
                afr[mt][3] = As[(r + 8) * SST + k0 + lk + 4];
            }
            #pragma unroll
            for (int nt = 0; nt < 4; ++nt) {
                const int rn = n_w + nt * 8 + lr4;
                bfr[nt][0] = Bs[rn * SST + k0 + lk];
                bfr[nt][1] = Bs[rn * SST + k0 + lk + 4];
            }
            #pragma unroll
            for (int mt = 0; mt < 4; ++mt)
                #pragma unroll
                for (int nt = 0; nt < 4; ++nt)
                    MMA_TF32(acc[mt][nt], afr[mt], bfr[nt]);
        }

        // stage next tile to the other buffer
        if (kt + 1 < nk) {
            uint32_t* Ad = Abuf[cur ^ 1];
            uint32_t* Bd = Bbuf[cur ^ 1];
            #pragma unroll
            for (int i = 0; i < 4; ++i) {
                const int idx = tid + i * 256;
                const int row = idx >> 3;
                const int c4  = (idx & 7) << 2;
                uint4 ua = { f2tf32(ar[i].x), f2tf32(ar[i].y), f2tf32(ar[i].z), f2tf32(ar[i].w) };
                uint4 ub = { f2tf32(br[i].x), f2tf32(br[i].y), f2tf32(br[i].z), f2tf32(br[i].w) };
                *(uint4*)&Ad[row * SST + c4] = ua;
                *(uint4*)&Bd[row * SST + c4] = ub;
            }
        }
        __syncthreads();
        cur ^= 1;
    }

    // ---- epilogue ----
    #pragma unroll
    for (int mt = 0; mt < 4; ++mt) {
        #pragma unroll
        for (int half = 0; half < 2; ++half) {
            const int row = bm + m_w + mt * 16 + lr4 + half * 8;
            #pragma unroll
            for (int nt = 0; nt < 4; ++nt) {
                const int col = bn + n_w + nt * 8 + 2 * lk;
                const size_t idx = (size_t)row * N + col;
                float v0 = acc[mt][nt][half * 2 + 0];
                float v1 = acc[mt][nt][half * 2 + 1];
                if (EPI == 0) {
                    if (aux) { v0 += aux[col]; v1 += aux[col + 1]; }
                } else if (EPI == 1) {
                    const float2 r = *(const float2*)(aux + idx);
                    v0 += r.x; v1 += r.y;
                } else {
                    const float2 g = *(const float2*)(aux + idx);
                    v0 *= g.x / (1.0f + __expf(-g.x));
                    v1 *= g.y / (1.0f + __expf(-g.y));
                }
                float2 r; r.x = v0; r.y = v1;
                *(float2*)(C + idx) = r;
            }
        }
    }
}

// ---------------------------------------------------------------------------
// Flash attention (fp32, causal, GQA h -> h % KVH)  — unchanged from R1
// ---------------------------------------------------------------------------
#define QT 64
#define KT 64
#define SSTRIDE 132
#define PSTRIDE 65

__global__ void __launch_bounds__(256) flash_kernel(
    const float* __restrict__ Qb, const float* __restrict__ Kb,
    const float* __restrict__ Vb, float* __restrict__ Ob)
{
    extern __shared__ float sm[];
    float* Qs = sm;
    float* Ks = Qs + QT * SSTRIDE;
    float* Vs = Ks + KT * SSTRIDE;
    float* Ps = Vs + KT * SSTRIDE;

    const int qt   = blockIdx.x;
    const int hh   = blockIdx.y;
    const int b    = blockIdx.z;
    const int g    = hh & (KVHEAD - 1);
    const int tid  = threadIdx.x;
    const int warp = tid >> 5;
    const int lane = tid & 31;
    const int r0   = warp * 8;
    const int qbase = qt * QT;

    const float* qptr = Qb + ((size_t)b * SEQ + qbase) * D_MODEL + hh * HDIM;
    #pragma unroll
    for (int it = 0; it < 8; ++it) {
        const int idx = tid + it * 256;
        const int row = idx >> 5;
        const int c4  = (idx & 31) << 2;
        float4 v = *(const float4*)(qptr + (size_t)row * D_MODEL + c4);
        float* d = &Qs[row * SSTRIDE + c4];
        d[0] = v.x; d[1] = v.y; d[2] = v.z; d[3] = v.w;
    }

    float acc[8][4];
    float m_i[8], l_i[8];
    #pragma unroll
    for (int i = 0; i < 8; ++i) {
        m_i[i] = -1e30f; l_i[i] = 0.f;
        acc[i][0] = acc[i][1] = acc[i][2] = acc[i][3] = 0.f;
    }
    const float scale = 0.08838834764831845f;
    const int c0 = lane * 2, c1 = c0 + 1;

    for (int kt = 0; kt <= qt; ++kt) {
        __syncthreads();
        const float* kptr = Kb + ((size_t)b * SEQ + kt * KT) * KD + g * HDIM;
        const float* vptr = Vb + ((size_t)b * SEQ + kt * KT) * KD + g * HDIM;
        #pragma unroll
        for (int it = 0; it < 8; ++it) {
            const int idx = tid + it * 256;
            const int row = idx >> 5;
            const int c4  = (idx & 31) << 2;
            float4 kv = *(const float4*)(kptr + (size_t)row * KD + c4);
            float* dk = &Ks[row * SSTRIDE + c4];
            dk[0] = kv.x; dk[1] = kv.y; dk[2] = kv.z; dk[3] = kv.w;
            float4 vv = *(const float4*)(vptr + (size_t)row * KD + c4);
            float* dv = &Vs[row * SSTRIDE + c4];
            dv[0] = vv.x; dv[1] = vv.y; dv[2] = vv.z; dv[3] = vv.w;
        }
        __syncthreads();

        float s0[8], s1[8];
        #pragma unroll
        for (int i = 0; i < 8; ++i) { s0[i] = 0.f; s1[i] = 0.f; }
        #pragma unroll 8
        for (int kk = 0; kk < HDIM; kk += 4) {
            const float4 k0 = *(const float4*)&Ks[c0 * SSTRIDE + kk];
            const float4 k1 = *(const float4*)&Ks[c1 * SSTRIDE + kk];
            #pragma unroll
            for (int i = 0; i < 8; ++i) {
                const float4 q4 = *(const float4*)&Qs[(r0 + i) * SSTRIDE + kk];
                s0[i] += q4.x * k0.x + q4.y * k0.y + q4.z * k0.z + q4.w * k0.w;
                s1[i] += q4.x * k1.x + q4.y * k1.y + q4.z * k1.z + q4.w * k1.w;
            }
        }

        #pragma unroll
        for (int i = 0; i < 8; ++i) {
            const int qi  = qbase + r0 + i;
            const int k0i = kt * KT + c0;
            const int k1i = k0i + 1;
            float v0 = s0[i] * scale;
            float v1 = s1[i] * scale;
            if (k0i > qi) v0 = -1e30f;
            if (k1i > qi) v1 = -1e30f;
            float mx = fmaxf(v0, v1);
            #pragma unroll
            for (int off = 16; off; off >>= 1)
                mx = fmaxf(mx, __shfl_xor_sync(0xffffffffu, mx, off));
            const float mnew = fmaxf(m_i[i], mx);
            const float p0 = __expf(v0 - mnew);
            const float p1 = __expf(v1 - mnew);
            float ps = p0 + p1;
            #pragma unroll
            for (int off = 16; off; off >>= 1)
                ps += __shfl_xor_sync(0xffffffffu, ps, off);
            const float alpha = __expf(m_i[i] - mnew);
            l_i[i] = l_i[i] * alpha + ps;
            m_i[i] = mnew;
            acc[i][0] *= alpha; acc[i][1] *= alpha;
            acc[i][2] *= alpha; acc[i][3] *= alpha;
            Ps[(r0 + i) * PSTRIDE + c0] = p0;
            Ps[(r0 + i) * PSTRIDE + c1] = p1;
        }
        __syncwarp();

        #pragma unroll 4
        for (int k = 0; k < KT; ++k) {
            const float4 vv = *(const float4*)&Vs[k * SSTRIDE + lane * 4];
            #pragma unroll
            for (int i = 0; i < 8; ++i) {
                const float p = Ps[(r0 + i) * PSTRIDE + k];
                acc[i][0] += p * vv.x; acc[i][1] += p * vv.y;
                acc[i][2] += p * vv.z; acc[i][3] += p * vv.w;
            }
        }
    }

    float* optr = Ob + ((size_t)b * SEQ + qbase) * D_MODEL + hh * HDIM;
    #pragma unroll
    for (int i = 0; i < 8; ++i) {
        const float inv = 1.0f / l_i[i];
        float4 o;
        o.x = acc[i][0] * inv; o.y = acc[i][1] * inv;
        o.z = acc[i][2] * inv; o.w = acc[i][3] * inv;
        *(float4*)(optr + (size_t)(r0 + i) * D_MODEL + lane * 4) = o;
    }
}

// ---------------------------------------------------------------------------
// Launch sequence
// ---------------------------------------------------------------------------
extern "C" void kernel_launch(void* const* d_in, const int* in_sizes, int n_in,
                              void* d_out, int out_size)
{
    const float* x      = (const float*)d_in[0];
    const float* ln1_w  = (const float*)d_in[1];
    const float* q_w    = (const float*)d_in[2];
    const float* q_b    = (const float*)d_in[3];
    const float* k_w    = (const float*)d_in[4];
    const float* k_b    = (const float*)d_in[5];
    const float* v_w    = (const float*)d_in[6];
    const float* v_b    = (const float*)d_in[7];
    const float* o_w    = (const float*)d_in[8];
    const float* ln2_w  = (const float*)d_in[9];
    const float* gate_w = (const float*)d_in[10];
    const float* up_w   = (const float*)d_in[11];
    const float* down_w = (const float*)d_in[12];
    float* out = (float*)d_out;

    float *h, *q, *k, *v, *act;
    cudaGetSymbolAddress((void**)&h,   g_h);
    cudaGetSymbolAddress((void**)&q,   g_q);
    cudaGetSymbolAddress((void**)&k,   g_k);
    cudaGetSymbolAddress((void**)&v,   g_v);
    cudaGetSymbolAddress((void**)&act, g_act);

    static int configured = 0;
    if (!configured) {
        cudaFuncSetAttribute(sgemm_tf32_kernel<0>,
                             cudaFuncAttributeMaxDynamicSharedMemorySize, GEMM_SMEM);
        cudaFuncSetAttribute(sgemm_tf32_kernel<1>,
                             cudaFuncAttributeMaxDynamicSharedMemorySize, GEMM_SMEM);
        cudaFuncSetAttribute(sgemm_tf32_kernel<2>,
                             cudaFuncAttributeMaxDynamicSharedMemorySize, GEMM_SMEM);
        const int fsmem = (3 * QT * SSTRIDE + QT * PSTRIDE) * (int)sizeof(float);
        cudaFuncSetAttribute(flash_kernel,
                             cudaFuncAttributeMaxDynamicSharedMemorySize, fsmem);
        configured = 1;
    }
    const int fsmem = (3 * QT * SSTRIDE + QT * PSTRIDE) * (int)sizeof(float);

    // 1. h = rmsnorm(x, ln1_w)
    rmsnorm_kernel<<<MTOT, 256>>>(x, ln1_w, h);

    // 2-4. q/k/v projections (+bias)
    sgemm_tf32_kernel<0><<<dim3(D_MODEL / BN, MTOT / BM), 256, GEMM_SMEM>>>(h, q_w, q_b, q, MTOT, D_MODEL, D_MODEL);
    sgemm_tf32_kernel<0><<<dim3(KD / BN,      MTOT / BM), 256, GEMM_SMEM>>>(h, k_w, k_b, k, MTOT, KD, D_MODEL);
    sgemm_tf32_kernel<0><<<dim3(KD / BN,      MTOT / BM), 256, GEMM_SMEM>>>(h, v_w, v_b, v, MTOT, KD, D_MODEL);

    // 5. flash attention -> reuse h as attention output
    flash_kernel<<<dim3(SEQ / QT, NHEAD, BATCH), 256, fsmem>>>(q, k, v, h);

    // 6. x1 = x + attn @ o_w^T   (into d_out)
    sgemm_tf32_kernel<1><<<dim3(D_MODEL / BN, MTOT / BM), 256, GEMM_SMEM>>>(h, o_w, x, out, MTOT, D_MODEL, D_MODEL);

    // 7. h2 = rmsnorm(x1, ln2_w) -> reuse q
    rmsnorm_kernel<<<MTOT, 256>>>(out, ln2_w, q);

    // 8. gate = h2 @ gate_w^T
    sgemm_tf32_kernel<0><<<dim3(FF / BN, MTOT / BM), 256, GEMM_SMEM>>>(q, gate_w, (const float*)nullptr, act, MTOT, FF, D_MODEL);

    // 9. act = silu(gate) * (h2 @ up_w^T)
    sgemm_tf32_kernel<2><<<dim3(FF / BN, MTOT / BM), 256, GEMM_SMEM>>>(q, up_w, act, act, MTOT, FF, D_MODEL);

    // 10. out = x1 + act @ down_w^T
    sgemm_tf32_kernel<1><<<dim3(D_MODEL / BN, MTOT / BM), 256, GEMM_SMEM>>>(act, down_w, out, out, MTOT, D_MODEL, FF);
}

// round 3
// speedup vs baseline: 3.6032x; 1.8863x over previous
#include <cuda_runtime.h>
#include <math.h>
#include <stdint.h>

// Problem constants
#define D_MODEL 2048
#define SEQ     2048
#define BATCH   2
#define NHEAD   16
#define KVHEAD  4
#define HDIM    128
#define FF      5632
#define MTOT    (BATCH * SEQ)      // 4096 rows
#define KD      (KVHEAD * HDIM)    // 512

// ---------------------------------------------------------------------------
// Scratch (no cudaMalloc allowed)
// ---------------------------------------------------------------------------
__device__ float g_h  [MTOT * (size_t)D_MODEL];
__device__ float g_q  [MTOT * (size_t)D_MODEL];
__device__ float g_k  [MTOT * (size_t)KD];
__device__ float g_v  [MTOT * (size_t)KD];
__device__ float g_act[MTOT * (size_t)FF];
// rna-rounded weight copies (tf32-safe for cp.async raw loads)
__device__ float w_q[(size_t)D_MODEL * D_MODEL];
__device__ float w_k[(size_t)KD * D_MODEL];
__device__ float w_v[(size_t)KD * D_MODEL];
__device__ float w_o[(size_t)D_MODEL * D_MODEL];
__device__ float w_g[(size_t)FF * D_MODEL];
__device__ float w_u[(size_t)FF * D_MODEL];
__device__ float w_d[(size_t)D_MODEL * FF];

__device__ __forceinline__ uint32_t f2tf32(float x) {
    uint32_t u;
    asm("cvt.rna.tf32.f32 %0, %1;" : "=r"(u) : "f"(x));
    return u;
}
__device__ __forceinline__ float rnatf(float x) {
    return __uint_as_float(f2tf32(x));
}

#define MMA_TF32(d, a, b)                                                   \
    asm volatile(                                                           \
        "mma.sync.aligned.m16n8k8.row.col.f32.tf32.tf32.f32 "               \
        "{%0,%1,%2,%3}, {%4,%5,%6,%7}, {%8,%9}, {%0,%1,%2,%3};"             \
        : "+f"(d[0]), "+f"(d[1]), "+f"(d[2]), "+f"(d[3])                    \
        : "r"(a[0]), "r"(a[1]), "r"(a[2]), "r"(a[3]), "r"(b[0]), "r"(b[1]))

__device__ __forceinline__ void cp_async16(void* dst, const void* src) {
    uint32_t s = (uint32_t)__cvta_generic_to_shared(dst);
    asm volatile("cp.async.cg.shared.global [%0], [%1], 16;\n" :: "r"(s), "l"(src));
}
__device__ __forceinline__ void cp_commit() {
    asm volatile("cp.async.commit_group;\n");
}
template<int N> __device__ __forceinline__ void cp_wait() {
    asm volatile("cp.async.wait_group %0;\n" :: "n"(N));
}

// ---------------------------------------------------------------------------
// Weight tf32-rounding pass
// ---------------------------------------------------------------------------
__global__ void __launch_bounds__(256) cvt4_kernel(
    const float4* __restrict__ s, float4* __restrict__ d, int n4)
{
    const int i = blockIdx.x * 256 + threadIdx.x;
    if (i >= n4) return;
    float4 v = s[i];
    v.x = rnatf(v.x); v.y = rnatf(v.y); v.z = rnatf(v.z); v.w = rnatf(v.w);
    d[i] = v;
}

// ---------------------------------------------------------------------------
// RMSNorm (rna-rounded output: feeds GEMM A operands)
// ---------------------------------------------------------------------------
__global__ void __launch_bounds__(256) rmsnorm_kernel(
    const float* __restrict__ x, const float* __restrict__ w,
    float* __restrict__ o)
{
    const int row = blockIdx.x;
    const float* xr = x + (size_t)row * D_MODEL;
    float* orow     = o + (size_t)row * D_MODEL;
    const int t = threadIdx.x;

    float4 a = *(const float4*)(xr + t * 4);
    float4 b = *(const float4*)(xr + 1024 + t * 4);
    float ss = a.x*a.x + a.y*a.y + a.z*a.z + a.w*a.w
             + b.x*b.x + b.y*b.y + b.z*b.z + b.w*b.w;
    #pragma unroll
    for (int off = 16; off; off >>= 1)
        ss += __shfl_xor_sync(0xffffffffu, ss, off);
    __shared__ float warp_s[8];
    if ((t & 31) == 0) warp_s[t >> 5] = ss;
    __syncthreads();
    float tot = 0.f;
    #pragma unroll
    for (int i = 0; i < 8; ++i) tot += warp_s[i];
    const float inv = rsqrtf(tot * (1.0f / D_MODEL) + 1e-6f);

    float4 w1 = *(const float4*)(w + t * 4);
    float4 w2 = *(const float4*)(w + 1024 + t * 4);
    float4 o1, o2;
    o1.x = rnatf(a.x * inv * w1.x); o1.y = rnatf(a.y * inv * w1.y);
    o1.z = rnatf(a.z * inv * w1.z); o1.w = rnatf(a.w * inv * w1.w);
    o2.x = rnatf(b.x * inv * w2.x); o2.y = rnatf(b.y * inv * w2.y);
    o2.z = rnatf(b.z * inv * w2.z); o2.w = rnatf(b.w * inv * w2.w);
    *(float4*)(orow + t * 4)        = o1;
    *(float4*)(orow + 1024 + t * 4) = o2;
}

// ---------------------------------------------------------------------------
// TF32 GEMM with cp.async 3-stage pipeline.
// C[M,N] = A[M,K] @ W[N,K]^T (+ epilogue). A,W must be pre-rna-rounded.
//   EPI 0: +bias[col] (aux may be null)   EPI 1: +aux[row,col]
//   EPI 2: silu(aux[row,col]) * acc
//   CVT 1: rna-round output (when it feeds another GEMM)
// ---------------------------------------------------------------------------
#define BK 32
#define GSST 36
#define STAGE_F (2 * 128 * GSST)           // floats per stage (A+B)
#define GEMM_SMEM (3 * STAGE_F * 4)        // 110592 bytes

template<int EPI, int CVT>
__global__ void __launch_bounds__(256, 2) gemm_tc(
    const float* __restrict__ A, const float* __restrict__ W,
    const float* aux, float* __restrict__ C,
    int M, int N, int K)
{
    extern __shared__ float sm[];
    const int tid  = threadIdx.x;
    const int warp = tid >> 5;
    const int lane = tid & 31;
    const int bm = blockIdx.y * 128;
    const int bn = blockIdx.x * 128;
    const int m_w = (warp >> 2) * 64;
    const int n_w = (warp & 3) * 32;
    const int lr4 = lane >> 2;
    const int lk  = lane & 3;

    const float* Ab = A + (size_t)bm * K;
    const float* Wb = W + (size_t)bn * K;

    float acc[4][4][4];
    #pragma unroll
    for (int mt = 0; mt < 4; ++mt)
        #pragma unroll
        for (int nt = 0; nt < 4; ++nt)
            #pragma unroll
            for (int r = 0; r < 4; ++r) acc[mt][nt][r] = 0.f;

    const int nk = K / BK;

    auto load_stage = [&](int st, int k0) {
        float* As = sm + st * STAGE_F;
        float* Bs = As + 128 * GSST;
        #pragma unroll
        for (int i = 0; i < 4; ++i) {
            const int idx = tid + i * 256;
            const int row = idx >> 3;
            const int c4  = (idx & 7) << 2;
            cp_async16(&As[row * GSST + c4], Ab + (size_t)row * K + k0 + c4);
            cp_async16(&Bs[row * GSST + c4], Wb + (size_t)row * K + k0 + c4);
        }
    };

    load_stage(0, 0);      cp_commit();
    load_stage(1, BK);     cp_commit();

    for (int kt = 0; kt < nk; ++kt) {
        cp_wait<1>();
        __syncthreads();
        if (kt + 2 < nk) load_stage((kt + 2) % 3, (kt + 2) * BK);
        cp_commit();

        const uint32_t* As = (const uint32_t*)(sm + (kt % 3) * STAGE_F);
        const uint32_t* Bs = As + 128 * GSST;
        #pragma unroll
        for (int kk = 0; kk < 4; ++kk) {
            const int k0 = kk * 8;
            uint32_t afr[4][4], bfr[4][2];
            #pragma unroll
            for (int mt = 0; mt < 4; ++mt) {
                const int r = m_w + mt * 16 + lr4;
                afr[mt][0] = As[r * GSST + k0 + lk];
                afr[mt][1] = As[(r + 8) * GSST + k0 + lk];
                afr[mt][2] = As[r * GSST + k0 + lk + 4];
                afr[mt][3] = As[(r + 8) * GSST + k0 + lk + 4];
            }
            #pragma unroll
            for (int nt = 0; nt < 4; ++nt) {
                const int rn = n_w + nt * 8 + lr4;
                bfr[nt][0] = Bs[rn * GSST + k0 + lk];
                bfr[nt][1] = Bs[rn * GSST + k0 + lk + 4];
            }
            #pragma unroll
            for (int mt = 0; mt < 4; ++mt)
                #pragma unroll
                for (int nt = 0; nt < 4; ++nt)
                    MMA_TF32(acc[mt][nt], afr[mt], bfr[nt]);
        }
    }

    // epilogue
    #pragma unroll
    for (int mt = 0; mt < 4; ++mt) {
        #pragma unroll
        for (int half = 0; half < 2; ++half) {
            const int row = bm + m_w + mt * 16 + lr4 + half * 8;
            #pragma unroll
            for (int nt = 0; nt < 4; ++nt) {
                const int col = bn + n_w + nt * 8 + 2 * lk;
                const size_t idx = (size_t)row * N + col;
                float v0 = acc[mt][nt][half * 2 + 0];
                float v1 = acc[mt][nt][half * 2 + 1];
                if (EPI == 0) {
                    if (aux) { v0 += aux[col]; v1 += aux[col + 1]; }
                } else if (EPI == 1) {
                    const float2 r = *(const float2*)(aux + idx);
                    v0 += r.x; v1 += r.y;
                } else {
                    const float2 g = *(const float2*)(aux + idx);
                    v0 *= g.x / (1.0f + __expf(-g.x));
                    v1 *= g.y / (1.0f + __expf(-g.y));
                }
                if (CVT) { v0 = rnatf(v0); v1 = rnatf(v1); }
                float2 r; r.x = v0; r.y = v1;
                *(float2*)(C + idx) = r;
            }
        }
    }
}

// ---------------------------------------------------------------------------
// Flash attention on tensor cores (tf32 mma, fp32 accum, causal, GQA)
// Q tile 128 rows, K/V tiles 64 rows, 8 warps (16 q-rows each).
// Smem strides: Q/K/P stride === 4 (mod 32), V stride === 8 -> all fragment
// LDS conflict-free.
// ---------------------------------------------------------------------------
#define FQT 128
#define FKT 64
#define QST 132
#define KST 132
#define VST 136
#define PST 68
#define FLASH_SMEM ((FQT*QST + FKT*KST + FKT*VST + FQT*PST) * 4)  // 171008

__global__ void __launch_bounds__(256) flash_tc_kernel(
    const float* __restrict__ Qb, const float* __restrict__ Kb,
    const float* __restrict__ Vb, float* __restrict__ Ob)
{
    extern __shared__ float fs[];
    float* Qs = fs;
    float* Ks = Qs + FQT * QST;
    float* Vs = Ks + FKT * KST;
    float* Ps = Vs + FKT * VST;

    const int bx   = blockIdx.x;           // q tile (128 rows)
    const int hh   = blockIdx.y;
    const int b    = blockIdx.z;
    const int g    = hh & (KVHEAD - 1);
    const int tid  = threadIdx.x;
    const int warp = tid >> 5;
    const int lane = tid & 31;
    const int lr   = lane >> 2;            // 0..7
    const int lq   = lane & 3;             // 0..3
    const int mb   = warp * 16;            // warp's m base in tile
    const int qbase = bx * FQT;
    const float scale = 0.08838834764831845f;   // 1/sqrt(128)

    // Load Q tile [128 x 128], scaled + rna-rounded
    const float* qptr = Qb + ((size_t)b * SEQ + qbase) * D_MODEL + hh * HDIM;
    #pragma unroll
    for (int it = 0; it < 16; ++it) {
        const int idx = tid + it * 256;
        const int row = idx >> 5;
        const int c4  = (idx & 31) << 2;
        float4 v = *(const float4*)(qptr + (size_t)row * D_MODEL + c4);
        float* d = &Qs[row * QST + c4];
        d[0] = rnatf(v.x * scale); d[1] = rnatf(v.y * scale);
        d[2] = rnatf(v.z * scale); d[3] = rnatf(v.w * scale);
    }

    float o[16][4];
    #pragma unroll
    for (int nt = 0; nt < 16; ++nt)
        o[nt][0] = o[nt][1] = o[nt][2] = o[nt][3] = 0.f;
    float m0 = -1e30f, m1 = -1e30f, l0 = 0.f, l1 = 0.f;

    const int r0g = qbase + mb + lr;
    const int r1g = r0g + 8;
    const int nkt = 2 * (bx + 1);

    for (int kt = 0; kt < nkt; ++kt) {
        __syncthreads();   // protects K/V reuse; covers Q visibility at kt=0
        const int ktb = kt * FKT;
        const float* kptr = Kb + ((size_t)b * SEQ + ktb) * KD + g * HDIM;
        const float* vptr = Vb + ((size_t)b * SEQ + ktb) * KD + g * HDIM;
        #pragma unroll
        for (int it = 0; it < 8; ++it) {
            const int idx = tid + it * 256;
            const int row = idx >> 5;
            const int c4  = (idx & 31) << 2;
            float4 kv = *(const float4*)(kptr + (size_t)row * KD + c4);
            float* dk = &Ks[row * KST + c4];
            dk[0] = rnatf(kv.x); dk[1] = rnatf(kv.y);
            dk[2] = rnatf(kv.z); dk[3] = rnatf(kv.w);
            float4 vv = *(const float4*)(vptr + (size_t)row * KD + c4);
            float* dv = &Vs[row * VST + c4];
            dv[0] = rnatf(vv.x); dv[1] = rnatf(vv.y);
            dv[2] = rnatf(vv.z); dv[3] = rnatf(vv.w);
        }
        __syncthreads();

        // ---- S = Q K^T  (16 x 64 per warp) ----
        float s[8][4];
        #pragma unroll
        for (int nt = 0; nt < 8; ++nt)
            s[nt][0] = s[nt][1] = s[nt][2] = s[nt][3] = 0.f;
        #pragma unroll
        for (int kk = 0; kk < 16; ++kk) {
            const int k0 = kk * 8;
            uint32_t a[4];
            a[0] = __float_as_uint(Qs[(mb + lr)     * QST + k0 + lq]);
            a[1] = __float_as_uint(Qs[(mb + lr + 8) * QST + k0 + lq]);
            a[2] = __float_as_uint(Qs[(mb + lr)     * QST + k0 + lq + 4]);
            a[3] = __float_as_uint(Qs[(mb + lr + 8) * QST + k0 + lq + 4]);
            #pragma unroll
            for (int nt = 0; nt < 8; ++nt) {
                uint32_t bfr[2];
                bfr[0] = __float_as_uint(Ks[(nt * 8 + lr) * KST + k0 + lq]);
                bfr[1] = __float_as_uint(Ks[(nt * 8 + lr) * KST + k0 + lq + 4]);
                MMA_TF32(s[nt], a, bfr);
            }
        }

        // ---- causal mask + online softmax ----
        float mx0 = -1e30f, mx1 = -1e30f;
        #pragma unroll
        for (int nt = 0; nt < 8; ++nt) {
            const int c = ktb + nt * 8 + 2 * lq;
            if (c     > r0g) s[nt][0] = -1e30f;
            if (c + 1 > r0g) s[nt][1] = -1e30f;
            if (c     > r1g) s[nt][2] = -1e30f;
            if (c + 1 > r1g) s[nt][3] = -1e30f;
            mx0 = fmaxf(mx0, fmaxf(s[nt][0], s[nt][1]));
            mx1 = fmaxf(mx1, fmaxf(s[nt][2], s[nt][3]));
        }
        mx0 = fmaxf(mx0, __shfl_xor_sync(0xffffffffu, mx0, 1));
        mx0 = fmaxf(mx0, __shfl_xor_sync(0xffffffffu, mx0, 2));
        mx1 = fmaxf(mx1, __shfl_xor_sync(0xffffffffu, mx1, 1));
        mx1 = fmaxf(mx1, __shfl_xor_sync(0xffffffffu, mx1, 2));
        const float mn0 = fmaxf(m0, mx0), mn1 = fmaxf(m1, mx1);
        const float al0 = __expf(m0 - mn0), al1 = __expf(m1 - mn1);
        m0 = mn0; m1 = mn1;

        float ps0 = 0.f, ps1 = 0.f;
        #pragma unroll
        for (int nt = 0; nt < 8; ++nt) {
            const float p0 = __expf(s[nt][0] - mn0);
            const float p1 = __expf(s[nt][1] - mn0);
            const float p2 = __expf(s[nt][2] - mn1);
            const float p3 = __expf(s[nt][3] - mn1);
            ps0 += p0 + p1; ps1 += p2 + p3;
            float2 lo; lo.x = rnatf(p0); lo.y = rnatf(p1);
            float2 hi; hi.x = rnatf(p2); hi.y = rnatf(p3);
            *(float2*)&Ps[(mb + lr)     * PST + nt * 8 + 2 * lq] = lo;
            *(float2*)&Ps[(mb + lr + 8) * PST + nt * 8 + 2 * lq] = hi;
        }
        ps0 += __shfl_xor_sync(0xffffffffu, ps0, 1);
        ps0 += __shfl_xor_sync(0xffffffffu, ps0, 2);
        ps1 += __shfl_xor_sync(0xffffffffu, ps1, 1);
        ps1 += __shfl_xor_sync(0xffffffffu, ps1, 2);
        l0 = l0 * al0 + ps0;
        l1 = l1 * al1 + ps1;

        #pragma unroll
        for (int nt = 0; nt < 16; ++nt) {
            o[nt][0] *= al0; o[nt][1] *= al0;
            o[nt][2] *= al1; o[nt][3] *= al1;
        }
        __syncwarp();   // P rows are warp-private: warp-scope ordering suffices

        // ---- O += P V  (16 x 128 per warp, K=64) ----
        #pragma unroll
        for (int kk = 0; kk < 8; ++kk) {
            const int k0 = kk * 8;
            uint32_t a[4];
            a[0] = __float_as_uint(Ps[(mb + lr)     * PST + k0 + lq]);
            a[1] = __float_as_uint(Ps[(mb + lr + 8) * PST + k0 + lq]);
            a[2] = __float_as_uint(Ps[(mb + lr)     * PST + k0 + lq + 4]);
            a[3] = __float_as_uint(Ps[(mb + lr + 8) * PST + k0 + lq + 4]);
            #pragma unroll
            for (int nt = 0; nt < 16; ++nt) {
                uint32_t bfr[2];
                bfr[0] = __float_as_uint(Vs[(k0 + lq)     * VST + nt * 8 + lr]);
                bfr[1] = __float_as_uint(Vs[(k0 + lq + 4) * VST + nt * 8 + lr]);
                MMA_TF32(o[nt], a, bfr);
            }
        }
    }

    // ---- write O (normalized, rna-rounded: feeds o-proj GEMM) ----
    const float i0 = 1.0f / l0, i1 = 1.0f / l1;
    float* op = Ob + ((size_t)b * SEQ + qbase + mb) * D_MODEL + hh * HDIM;
    #pragma unroll
    for (int nt = 0; nt < 16; ++nt) {
        const int col = nt * 8 + 2 * lq;
        float2 lo; lo.x = rnatf(o[nt][0] * i0); lo.y = rnatf(o[nt][1] * i0);
        float2 hi; hi.x = rnatf(o[nt][2] * i1); hi.y = rnatf(o[nt][3] * i1);
        *(float2*)(op + (size_t)lr * D_MODEL + col)       = lo;
        *(float2*)(op + (size_t)(lr + 8) * D_MODEL + col) = hi;
    }
}

// ---------------------------------------------------------------------------
// Launch sequence
// ---------------------------------------------------------------------------
extern "C" void kernel_launch(void* const* d_in, const int* in_sizes, int n_in,
                              void* d_out, int out_size)
{
    const float* x      = (const float*)d_in[0];
    const float* ln1_w  = (const float*)d_in[1];
    const float* q_w    = (const float*)d_in[2];
    const float* q_b    = (const float*)d_in[3];
    const float* k_w    = (const float*)d_in[4];
    const float* k_b    = (const float*)d_in[5];
    const float* v_w    = (const float*)d_in[6];
    const float* v_b    = (const float*)d_in[7];
    const float* o_w    = (const float*)d_in[8];
    const float* ln2_w  = (const float*)d_in[9];
    const float* gate_w = (const float*)d_in[10];
    const float* up_w   = (const float*)d_in[11];
    const float* down_w = (const float*)d_in[12];
    float* out = (float*)d_out;

    float *h, *q, *k, *v, *act;
    float *wq, *wk, *wv, *wo, *wg, *wu, *wd;
    cudaGetSymbolAddress((void**)&h,   g_h);
    cudaGetSymbolAddress((void**)&q,   g_q);
    cudaGetSymbolAddress((void**)&k,   g_k);
    cudaGetSymbolAddress((void**)&v,   g_v);
    cudaGetSymbolAddress((void**)&act, g_act);
    cudaGetSymbolAddress((void**)&wq,  w_q);
    cudaGetSymbolAddress((void**)&wk,  w_k);
    cudaGetSymbolAddress((void**)&wv,  w_v);
    cudaGetSymbolAddress((void**)&wo,  w_o);
    cudaGetSymbolAddress((void**)&wg,  w_g);
    cudaGetSymbolAddress((void**)&wu,  w_u);
    cudaGetSymbolAddress((void**)&wd,  w_d);

    cudaFuncSetAttribute(gemm_tc<0,0>, cudaFuncAttributeMaxDynamicSharedMemorySize, GEMM_SMEM);
    cudaFuncSetAttribute(gemm_tc<1,0>, cudaFuncAttributeMaxDynamicSharedMemorySize, GEMM_SMEM);
    cudaFuncSetAttribute(gemm_tc<2,1>, cudaFuncAttributeMaxDynamicSharedMemorySize, GEMM_SMEM);
    cudaFuncSetAttribute(flash_tc_kernel, cudaFuncAttributeMaxDynamicSharedMemorySize, FLASH_SMEM);

    // 0. rna-round all weights into scratch copies
    {
        struct { const float* s; float* d; int n; } cv[7] = {
            { q_w,    wq, D_MODEL * D_MODEL }, { k_w, wk, KD * D_MODEL },
            { v_w,    wv, KD * D_MODEL },      { o_w, wo, D_MODEL * D_MODEL },
            { gate_w, wg, FF * D_MODEL },      { up_w, wu, FF * D_MODEL },
            { down_w, wd, D_MODEL * FF },
        };
        for (int i = 0; i < 7; ++i) {
            const int n4 = cv[i].n / 4;
            cvt4_kernel<<<(n4 + 255) / 256, 256>>>(
                (const float4*)cv[i].s, (float4*)cv[i].d, n4);
        }
    }

    // 1. h = rmsnorm(x, ln1_w)  [rna-rounded]
    rmsnorm_kernel<<<MTOT, 256>>>(x, ln1_w, h);

    // 2-4. q/k/v projections (+bias)
    gemm_tc<0,0><<<dim3(D_MODEL/128, MTOT/128), 256, GEMM_SMEM>>>(h, wq, q_b, q, MTOT, D_MODEL, D_MODEL);
    gemm_tc<0,0><<<dim3(KD/128,      MTOT/128), 256, GEMM_SMEM>>>(h, wk, k_b, k, MTOT, KD, D_MODEL);
    gemm_tc<0,0><<<dim3(KD/128,      MTOT/128), 256, GEMM_SMEM>>>(h, wv, v_b, v, MTOT, KD, D_MODEL);

    // 5. flash attention (tensor cores) -> h
    flash_tc_kernel<<<dim3(SEQ/FQT, NHEAD, BATCH), 256, FLASH_SMEM>>>(q, k, v, h);

    // 6. x1 = x + attn @ o_w^T -> d_out
    gemm_tc<1,0><<<dim3(D_MODEL/128, MTOT/128), 256, GEMM_SMEM>>>(h, wo, x, out, MTOT, D_MODEL, D_MODEL);

    // 7. h2 = rmsnorm(x1, ln2_w) -> q  [rna-rounded]
    rmsnorm_kernel<<<MTOT, 256>>>(out, ln2_w, q);

    // 8. gate = h2 @ gate_w^T  (full precision out: feeds silu only)
    gemm_tc<0,0><<<dim3(FF/128, MTOT/128), 256, GEMM_SMEM>>>(q, wg, (const float*)nullptr, act, MTOT, FF, D_MODEL);

    // 9. act = silu(gate) * (h2 @ up_w^T)  [rna-rounded: feeds down GEMM]
    gemm_tc<2,1><<<dim3(FF/128, MTOT/128), 256, GEMM_SMEM>>>(q, wu, act, act, MTOT, FF, D_MODEL);

    // 10. out = x1 + act @ down_w^T
    gemm_tc<1,0><<<dim3(D_MODEL/128, MTOT/128), 256, GEMM_SMEM>>>(act, wd, out, out, MTOT, D_MODEL, FF);
}

// round 4
// speedup vs baseline: 3.7359x; 1.0368x over previous
#include <cuda_runtime.h>
#include <math.h>
#include <stdint.h>

// Problem constants
#define D_MODEL 2048
#define SEQ     2048
#define BATCH   2
#define NHEAD   16
#define KVHEAD  4
#define HDIM    128
#define FF      5632
#define MTOT    (BATCH * SEQ)      // 4096 rows
#define KD      (KVHEAD * HDIM)    // 512

// ---------------------------------------------------------------------------
// Scratch (no cudaMalloc allowed)
// ---------------------------------------------------------------------------
__device__ float g_h  [MTOT * (size_t)D_MODEL];
__device__ float g_q  [MTOT * (size_t)D_MODEL];
__device__ float g_k  [MTOT * (size_t)KD];
__device__ float g_v  [MTOT * (size_t)KD];
__device__ float g_act[MTOT * (size_t)FF];
// rna-rounded weight copies (tf32-safe for cp.async raw loads)
__device__ float w_q[(size_t)D_MODEL * D_MODEL];
__device__ float w_k[(size_t)KD * D_MODEL];
__device__ float w_v[(size_t)KD * D_MODEL];
__device__ float w_o[(size_t)D_MODEL * D_MODEL];
__device__ float w_g[(size_t)FF * D_MODEL];
__device__ float w_u[(size_t)FF * D_MODEL];
__device__ float w_d[(size_t)D_MODEL * FF];

__device__ __forceinline__ uint32_t f2tf32(float x) {
    uint32_t u;
    asm("cvt.rna.tf32.f32 %0, %1;" : "=r"(u) : "f"(x));
    return u;
}
__device__ __forceinline__ float rnatf(float x) {
    return __uint_as_float(f2tf32(x));
}

#define MMA_TF32(d, a, b)                                                   \
    asm volatile(                                                           \
        "mma.sync.aligned.m16n8k8.row.col.f32.tf32.tf32.f32 "               \
        "{%0,%1,%2,%3}, {%4,%5,%6,%7}, {%8,%9}, {%0,%1,%2,%3};"             \
        : "+f"(d[0]), "+f"(d[1]), "+f"(d[2]), "+f"(d[3])                    \
        : "r"(a[0]), "r"(a[1]), "r"(a[2]), "r"(a[3]), "r"(b[0]), "r"(b[1]))

__device__ __forceinline__ void cp_async16(void* dst, const void* src) {
    uint32_t s = (uint32_t)__cvta_generic_to_shared(dst);
    asm volatile("cp.async.cg.shared.global [%0], [%1], 16;\n" :: "r"(s), "l"(src));
}
__device__ __forceinline__ void cp_commit() {
    asm volatile("cp.async.commit_group;\n");
}
template<int N> __device__ __forceinline__ void cp_wait() {
    asm volatile("cp.async.wait_group %0;\n" :: "n"(N));
}

// ---------------------------------------------------------------------------
// Weight tf32-rounding pass — ONE kernel for all 7 weight matrices.
// (Single launch keeps ncu's -s 5 -c 1 window on the flash kernel.)
// ---------------------------------------------------------------------------
struct CvtArgs {
    const float* s[7];
    float* d[7];
    int end4[7];   // prefix-sum (exclusive end) in float4 units
};

__global__ void __launch_bounds__(256) cvt_all_kernel(CvtArgs a, int total4)
{
    const int i = blockIdx.x * 256 + threadIdx.x;
    if (i >= total4) return;
    int j = 0;
    #pragma unroll
    for (int t = 0; t < 6; ++t)
        if (i >= a.end4[t]) j = t + 1;
    const int start = (j == 0) ? 0 : a.end4[j - 1];
    const float4* s = (const float4*)a.s[j];
    float4* d = (float4*)a.d[j];
    float4 v = s[i - start];
    v.x = rnatf(v.x); v.y = rnatf(v.y); v.z = rnatf(v.z); v.w = rnatf(v.w);
    d[i - start] = v;
}

// ---------------------------------------------------------------------------
// RMSNorm (rna-rounded output: feeds GEMM A operands)
// ---------------------------------------------------------------------------
__global__ void __launch_bounds__(256) rmsnorm_kernel(
    const float* __restrict__ x, const float* __restrict__ w,
    float* __restrict__ o)
{
    const int row = blockIdx.x;
    const float* xr = x + (size_t)row * D_MODEL;
    float* orow     = o + (size_t)row * D_MODEL;
    const int t = threadIdx.x;

    float4 a = *(const float4*)(xr + t * 4);
    float4 b = *(const float4*)(xr + 1024 + t * 4);
    float ss = a.x*a.x + a.y*a.y + a.z*a.z + a.w*a.w
             + b.x*b.x + b.y*b.y + b.z*b.z + b.w*b.w;
    #pragma unroll
    for (int off = 16; off; off >>= 1)
        ss += __shfl_xor_sync(0xffffffffu, ss, off);
    __shared__ float warp_s[8];
    if ((t & 31) == 0) warp_s[t >> 5] = ss;
    __syncthreads();
    float tot = 0.f;
    #pragma unroll
    for (int i = 0; i < 8; ++i) tot += warp_s[i];
    const float inv = rsqrtf(tot * (1.0f / D_MODEL) + 1e-6f);

    float4 w1 = *(const float4*)(w + t * 4);
    float4 w2 = *(const float4*)(w + 1024 + t * 4);
    float4 o1, o2;
    o1.x = rnatf(a.x * inv * w1.x); o1.y = rnatf(a.y * inv * w1.y);
    o1.z = rnatf(a.z * inv * w1.z); o1.w = rnatf(a.w * inv * w1.w);
    o2.x = rnatf(b.x * inv * w2.x); o2.y = rnatf(b.y * inv * w2.y);
    o2.z = rnatf(b.z * inv * w2.z); o2.w = rnatf(b.w * inv * w2.w);
    *(float4*)(orow + t * 4)        = o1;
    *(float4*)(orow + 1024 + t * 4) = o2;
}

// ---------------------------------------------------------------------------
// TF32 GEMM with cp.async 3-stage pipeline (unchanged from R3).
// ---------------------------------------------------------------------------
#define BK 32
#define GSST 36
#define STAGE_F (2 * 128 * GSST)
#define GEMM_SMEM (3 * STAGE_F * 4)

template<int EPI, int CVT>
__global__ void __launch_bounds__(256, 2) gemm_tc(
    const float* __restrict__ A, const float* __restrict__ W,
    const float* aux, float* __restrict__ C,
    int M, int N, int K)
{
    extern __shared__ float sm[];
    const int tid  = threadIdx.x;
    const int warp = tid >> 5;
    const int lane = tid & 31;
    const int bm = blockIdx.y * 128;
    const int bn = blockIdx.x * 128;
    const int m_w = (warp >> 2) * 64;
    const int n_w = (warp & 3) * 32;
    const int lr4 = lane >> 2;
    const int lk  = lane & 3;

    const float* Ab = A + (size_t)bm * K;
    const float* Wb = W + (size_t)bn * K;

    float acc[4][4][4];
    #pragma unroll
    for (int mt = 0; mt < 4; ++mt)
        #pragma unroll
        for (int nt = 0; nt < 4; ++nt)
            #pragma unroll
            for (int r = 0; r < 4; ++r) acc[mt][nt][r] = 0.f;

    const int nk = K / BK;

    auto load_stage = [&](int st, int k0) {
        float* As = sm + st * STAGE_F;
        float* Bs = As + 128 * GSST;
        #pragma unroll
        for (int i = 0; i < 4; ++i) {
            const int idx = tid + i * 256;
            const int row = idx >> 3;
            const int c4  = (idx & 7) << 2;
            cp_async16(&As[row * GSST + c4], Ab + (size_t)row * K + k0 + c4);
            cp_async16(&Bs[row * GSST + c4], Wb + (size_t)row * K + k0 + c4);
        }
    };

    load_stage(0, 0);      cp_commit();
    load_stage(1, BK);     cp_commit();

    for (int kt = 0; kt < nk; ++kt) {
        cp_wait<1>();
        __syncthreads();
        if (kt + 2 < nk) load_stage((kt + 2) % 3, (kt + 2) * BK);
        cp_commit();

        const uint32_t* As = (const uint32_t*)(sm + (kt % 3) * STAGE_F);
        const uint32_t* Bs = As + 128 * GSST;
        #pragma unroll
        for (int kk = 0; kk < 4; ++kk) {
            const int k0 = kk * 8;
            uint32_t afr[4][4], bfr[4][2];
            #pragma unroll
            for (int mt = 0; mt < 4; ++mt) {
                const int r = m_w + mt * 16 + lr4;
                afr[mt][0] = As[r * GSST + k0 + lk];
                afr[mt][1] = As[(r + 8) * GSST + k0 + lk];
                afr[mt][2] = As[r * GSST + k0 + lk + 4];
                afr[mt][3] = As[(r + 8) * GSST + k0 + lk + 4];
            }
            #pragma unroll
            for (int nt = 0; nt < 4; ++nt) {
                const int rn = n_w + nt * 8 + lr4;
                bfr[nt][0] = Bs[rn * GSST + k0 + lk];
                bfr[nt][1] = Bs[rn * GSST + k0 + lk + 4];
            }
            #pragma unroll
            for (int mt = 0; mt < 4; ++mt)
                #pragma unroll
                for (int nt = 0; nt < 4; ++nt)
                    MMA_TF32(acc[mt][nt], afr[mt], bfr[nt]);
        }
    }

    #pragma unroll
    for (int mt = 0; mt < 4; ++mt) {
        #pragma unroll
        for (int half = 0; half < 2; ++half) {
            const int row = bm + m_w + mt * 16 + lr4 + half * 8;
            #pragma unroll
            for (int nt = 0; nt < 4; ++nt) {
                const int col = bn + n_w + nt * 8 + 2 * lk;
                const size_t idx = (size_t)row * N + col;
                float v0 = acc[mt][nt][half * 2 + 0];
                float v1 = acc[mt][nt][half * 2 + 1];
                if (EPI == 0) {
                    if (aux) { v0 += aux[col]; v1 += aux[col + 1]; }
                } else if (EPI == 1) {
                    const float2 r = *(const float2*)(aux + idx);
                    v0 += r.x; v1 += r.y;
                } else {
                    const float2 g = *(const float2*)(aux + idx);
                    v0 *= g.x / (1.0f + __expf(-g.x));
                    v1 *= g.y / (1.0f + __expf(-g.y));
                }
                if (CVT) { v0 = rnatf(v0); v1 = rnatf(v1); }
                float2 r; r.x = v0; r.y = v1;
                *(float2*)(C + idx) = r;
            }
        }
    }
}

// ---------------------------------------------------------------------------
// Flash attention, tensor cores, cp.async double-buffered K/V, Q in regs.
// tf32 MMA reads raw fp32 (hardware truncation) -> no per-tile cvt pass.
// Q tile 128 rows, K/V tiles 64 rows, 8 warps.
// ---------------------------------------------------------------------------
#define FQT 128
#define FKT 64
#define KST 132
#define VST 136
#define PST 68
#define KV_STAGE (FKT * KST + FKT * VST)                 // 17152 floats
#define FLASH_SMEM ((2 * KV_STAGE + FQT * PST) * 4)      // 172032 bytes

__global__ void __launch_bounds__(256) flash_tc_kernel(
    const float* __restrict__ Qb, const float* __restrict__ Kb,
    const float* __restrict__ Vb, float* __restrict__ Ob)
{
    extern __shared__ float fs[];
    float* S0 = fs;                       // stage 0 (K then V)
    float* S1 = fs + KV_STAGE;            // stage 1
    float* Ps = fs + 2 * KV_STAGE;

    const int bx   = blockIdx.x;
    const int hh   = blockIdx.y;
    const int b    = blockIdx.z;
    const int g    = hh & (KVHEAD - 1);
    const int tid  = threadIdx.x;
    const int warp = tid >> 5;
    const int lane = tid & 31;
    const int lr   = lane >> 2;
    const int lq   = lane & 3;
    const int mb   = warp * 16;
    const int qbase = bx * FQT;
    const float scale = 0.08838834764831845f;   // 1/sqrt(128)

    // ---- stage Q through S0, extract fragments to registers ----
    const float* qptr = Qb + ((size_t)b * SEQ + qbase) * D_MODEL + hh * HDIM;
    #pragma unroll
    for (int it = 0; it < 16; ++it) {
        const int idx = tid + it * 256;
        const int row = idx >> 5;
        const int c4  = (idx & 31) << 2;
        float4 v = *(const float4*)(qptr + (size_t)row * D_MODEL + c4);
        float* d = &S0[row * KST + c4];
        d[0] = v.x * scale; d[1] = v.y * scale;
        d[2] = v.z * scale; d[3] = v.w * scale;
    }
    __syncthreads();
    uint32_t qf[16][4];
    #pragma unroll
    for (int kk = 0; kk < 16; ++kk) {
        const int k0 = kk * 8;
        qf[kk][0] = __float_as_uint(S0[(mb + lr)     * KST + k0 + lq]);
        qf[kk][1] = __float_as_uint(S0[(mb + lr + 8) * KST + k0 + lq]);
        qf[kk][2] = __float_as_uint(S0[(mb + lr)     * KST + k0 + lq + 4]);
        qf[kk][3] = __float_as_uint(S0[(mb + lr + 8) * KST + k0 + lq + 4]);
    }
    __syncthreads();

    const int nkt = 2 * (bx + 1);

    auto load_kv = [&](float* St, int ktb) {
        const float* kptr = Kb + ((size_t)b * SEQ + ktb) * KD + g * HDIM;
        const float* vptr = Vb + ((size_t)b * SEQ + ktb) * KD + g * HDIM;
        float* Kd = St;
        float* Vd = St + FKT * KST;
        #pragma unroll
        for (int it = 0; it < 8; ++it) {
            const int idx = tid + it * 256;
            const int row = idx >> 5;
            const int c4  = (idx & 31) << 2;
            cp_async16(&Kd[row * KST + c4], kptr + (size_t)row * KD + c4);
            cp_async16(&Vd[row * VST + c4], vptr + (size_t)row * KD + c4);
        }
    };

    load_kv(S0, 0);
    cp_commit();
    if (nkt > 1) load_kv(S1, FKT);
    cp_commit();

    float o[16][4];
    #pragma unroll
    for (int nt = 0; nt < 16; ++nt)
        o[nt][0] = o[nt][1] = o[nt][2] = o[nt][3] = 0.f;
    float m0 = -1e30f, m1 = -1e30f, l0 = 0.f, l1 = 0.f;
    const int r0g = qbase + mb + lr;
    const int r1g = r0g + 8;

    for (int kt = 0; kt < nkt; ++kt) {
        cp_wait<1>();
        __syncthreads();
        const float* St = (kt & 1) ? S1 : S0;
        const float* Ks = St;
        const float* Vs = St + FKT * KST;
        const int ktb = kt * FKT;

        // ---- S = Q K^T (16 x 64 per warp) ----
        float s[8][4];
        #pragma unroll
        for (int nt = 0; nt < 8; ++nt)
            s[nt][0] = s[nt][1] = s[nt][2] = s[nt][3] = 0.f;
        #pragma unroll
        for (int kk = 0; kk < 16; ++kk) {
            const int k0 = kk * 8;
            #pragma unroll
            for (int nt = 0; nt < 8; ++nt) {
                uint32_t bfr[2];
                bfr[0] = __float_as_uint(Ks[(nt * 8 + lr) * KST + k0 + lq]);
                bfr[1] = __float_as_uint(Ks[(nt * 8 + lr) * KST + k0 + lq + 4]);
                MMA_TF32(s[nt], qf[kk], bfr);
            }
        }

        // ---- causal mask + online softmax ----
        float mx0 = -1e30f, mx1 = -1e30f;
        #pragma unroll
        for (int nt = 0; nt < 8; ++nt) {
            const int c = ktb + nt * 8 + 2 * lq;
            if (c     > r0g) s[nt][0] = -1e30f;
            if (c + 1 > r0g) s[nt][1] = -1e30f;
            if (c     > r1g) s[nt][2] = -1e30f;
            if (c + 1 > r1g) s[nt][3] = -1e30f;
            mx0 = fmaxf(mx0, fmaxf(s[nt][0], s[nt][1]));
            mx1 = fmaxf(mx1, fmaxf(s[nt][2], s[nt][3]));
        }
        mx0 = fmaxf(mx0, __shfl_xor_sync(0xffffffffu, mx0, 1));
        mx0 = fmaxf(mx0, __shfl_xor_sync(0xffffffffu, mx0, 2));
        mx1 = fmaxf(mx1, __shfl_xor_sync(0xffffffffu, mx1, 1));
        mx1 = fmaxf(mx1, __shfl_xor_sync(0xffffffffu, mx1, 2));
        const float mn0 = fmaxf(m0, mx0), mn1 = fmaxf(m1, mx1);
        const float al0 = __expf(m0 - mn0), al1 = __expf(m1 - mn1);
        m0 = mn0; m1 = mn1;

        float ps0 = 0.f, ps1 = 0.f;
        #pragma unroll
        for (int nt = 0; nt < 8; ++nt) {
            const float p0 = __expf(s[nt][0] - mn0);
            const float p1 = __expf(s[nt][1] - mn0);
            const float p2 = __expf(s[nt][2] - mn1);
            const float p3 = __expf(s[nt][3] - mn1);
            ps0 += p0 + p1; ps1 += p2 + p3;
            float2 lo; lo.x = p0; lo.y = p1;
            float2 hi; hi.x = p2; hi.y = p3;
            *(float2*)&Ps[(mb + lr)     * PST + nt * 8 + 2 * lq] = lo;
            *(float2*)&Ps[(mb + lr + 8) * PST + nt * 8 + 2 * lq] = hi;
        }
        ps0 += __shfl_xor_sync(0xffffffffu, ps0, 1);
        ps0 += __shfl_xor_sync(0xffffffffu, ps0, 2);
        ps1 += __shfl_xor_sync(0xffffffffu, ps1, 1);
        ps1 += __shfl_xor_sync(0xffffffffu, ps1, 2);
        l0 = l0 * al0 + ps0;
        l1 = l1 * al1 + ps1;

        #pragma unroll
        for (int nt = 0; nt < 16; ++nt) {
            o[nt][0] *= al0; o[nt][1] *= al0;
            o[nt][2] *= al1; o[nt][3] *= al1;
        }
        __syncwarp();   // P rows are warp-private

        // ---- O += P V (16 x 128 per warp, K=64) ----
        #pragma unroll
        for (int kk = 0; kk < 8; ++kk) {
            const int k0 = kk * 8;
            uint32_t a[4];
            a[0] = __float_as_uint(Ps[(mb + lr)     * PST + k0 + lq]);
            a[1] = __float_as_uint(Ps[(mb + lr + 8) * PST + k0 + lq]);
            a[2] = __float_as_uint(Ps[(mb + lr)     * PST + k0 + lq + 4]);
            a[3] = __float_as_uint(Ps[(mb + lr + 8) * PST + k0 + lq + 4]);
            #pragma unroll
            for (int nt = 0; nt < 16; ++nt) {
                uint32_t bfr[2];
                bfr[0] = __float_as_uint(Vs[(k0 + lq)     * VST + nt * 8 + lr]);
                bfr[1] = __float_as_uint(Vs[(k0 + lq + 4) * VST + nt * 8 + lr]);
                MMA_TF32(o[nt], a, bfr);
            }
        }
        __syncthreads();  // all warps done with this stage before reload

        const int nx = kt + 2;
        if (nx < nkt) load_kv((nx & 1) ? S1 : S0, nx * FKT);
        cp_commit();
    }

    // ---- write O (normalized, rna-rounded: feeds o-proj GEMM) ----
    const float i0 = 1.0f / l0, i1 = 1.0f / l1;
    float* op = Ob + ((size_t)b * SEQ + qbase + mb) * D_MODEL + hh * HDIM;
    #pragma unroll
    for (int nt = 0; nt < 16; ++nt) {
        const int col = nt * 8 + 2 * lq;
        float2 lo; lo.x = rnatf(o[nt][0] * i0); lo.y = rnatf(o[nt][1] * i0);
        float2 hi; hi.x = rnatf(o[nt][2] * i1); hi.y = rnatf(o[nt][3] * i1);
        *(float2*)(op + (size_t)lr * D_MODEL + col)       = lo;
        *(float2*)(op + (size_t)(lr + 8) * D_MODEL + col) = hi;
    }
}

// ---------------------------------------------------------------------------
// Launch sequence
// ---------------------------------------------------------------------------
extern "C" void kernel_launch(void* const* d_in, const int* in_sizes, int n_in,
                              void* d_out, int out_size)
{
    const float* x      = (const float*)d_in[0];
    const float* ln1_w  = (const float*)d_in[1];
    const float* q_w    = (const float*)d_in[2];
    const float* q_b    = (const float*)d_in[3];
    const float* k_w    = (const float*)d_in[4];
    const float* k_b    = (const float*)d_in[5];
    const float* v_w    = (const float*)d_in[6];
    const float* v_b    = (const float*)d_in[7];
    const float* o_w    = (const float*)d_in[8];
    const float* ln2_w  = (const float*)d_in[9];
    const float* gate_w = (const float*)d_in[10];
    const float* up_w   = (const float*)d_in[11];
    const float* down_w = (const float*)d_in[12];
    float* out = (float*)d_out;

    float *h, *q, *k, *v, *act;
    float *wq, *wk, *wv, *wo, *wg, *wu, *wd;
    cudaGetSymbolAddress((void**)&h,   g_h);
    cudaGetSymbolAddress((void**)&q,   g_q);
    cudaGetSymbolAddress((void**)&k,   g_k);
    cudaGetSymbolAddress((void**)&v,   g_v);
    cudaGetSymbolAddress((void**)&act, g_act);
    cudaGetSymbolAddress((void**)&wq,  w_q);
    cudaGetSymbolAddress((void**)&wk,  w_k);
    cudaGetSymbolAddress((void**)&wv,  w_v);
    cudaGetSymbolAddress((void**)&wo,  w_o);
    cudaGetSymbolAddress((void**)&wg,  w_g);
    cudaGetSymbolAddress((void**)&wu,  w_u);
    cudaGetSymbolAddress((void**)&wd,  w_d);

    cudaFuncSetAttribute(gemm_tc<0,0>, cudaFuncAttributeMaxDynamicSharedMemorySize, GEMM_SMEM);
    cudaFuncSetAttribute(gemm_tc<1,0>, cudaFuncAttributeMaxDynamicSharedMemorySize, GEMM_SMEM);
    cudaFuncSetAttribute(gemm_tc<2,1>, cudaFuncAttributeMaxDynamicSharedMemorySize, GEMM_SMEM);
    cudaFuncSetAttribute(flash_tc_kernel, cudaFuncAttributeMaxDynamicSharedMemorySize, FLASH_SMEM);

    // 0. rna-round all 7 weight matrices (single launch)
    {
        CvtArgs a;
        const float* srcs[7] = { q_w, k_w, v_w, o_w, gate_w, up_w, down_w };
        float*       dsts[7] = { wq,  wk,  wv,  wo,  wg,     wu,   wd };
        const int    n[7]    = { D_MODEL*D_MODEL, KD*D_MODEL, KD*D_MODEL,
                                 D_MODEL*D_MODEL, FF*D_MODEL, FF*D_MODEL,
                                 D_MODEL*FF };
        int acc4 = 0;
        for (int i = 0; i < 7; ++i) {
            a.s[i] = srcs[i]; a.d[i] = dsts[i];
            acc4 += n[i] / 4; a.end4[i] = acc4;
        }
        cvt_all_kernel<<<(acc4 + 255) / 256, 256>>>(a, acc4);
    }

    // 1. h = rmsnorm(x, ln1_w)
    rmsnorm_kernel<<<MTOT, 256>>>(x, ln1_w, h);

    // 2-4. q/k/v projections (+bias)
    gemm_tc<0,0><<<dim3(D_MODEL/128, MTOT/128), 256, GEMM_SMEM>>>(h, wq, q_b, q, MTOT, D_MODEL, D_MODEL);
    gemm_tc<0,0><<<dim3(KD/128,      MTOT/128), 256, GEMM_SMEM>>>(h, wk, k_b, k, MTOT, KD, D_MODEL);
    gemm_tc<0,0><<<dim3(KD/128,      MTOT/128), 256, GEMM_SMEM>>>(h, wv, v_b, v, MTOT, KD, D_MODEL);

    // 5. flash attention (launch #5 -> ncu capture slot)
    flash_tc_kernel<<<dim3(SEQ/FQT, NHEAD, BATCH), 256, FLASH_SMEM>>>(q, k, v, h);

    // 6. x1 = x + attn @ o_w^T -> d_out
    gemm_tc<1,0><<<dim3(D_MODEL/128, MTOT/128), 256, GEMM_SMEM>>>(h, wo, x, out, MTOT, D_MODEL, D_MODEL);

    // 7. h2 = rmsnorm(x1, ln2_w) -> q
    rmsnorm_kernel<<<MTOT, 256>>>(out, ln2_w, q);

    // 8. gate = h2 @ gate_w^T
    gemm_tc<0,0><<<dim3(FF/128, MTOT/128), 256, GEMM_SMEM>>>(q, wg, (const float*)nullptr, act, MTOT, FF, D_MODEL);

    // 9. act = silu(gate) * (h2 @ up_w^T)
    gemm_tc<2,1><<<dim3(FF/128, MTOT/128), 256, GEMM_SMEM>>>(q, wu, act, act, MTOT, FF, D_MODEL);

    // 10. out = x1 + act @ down_w^T
    gemm_tc<1,0><<<dim3(D_MODEL/128, MTOT/128), 256, GEMM_SMEM>>>(act, wd, out, out, MTOT, D_MODEL, FF);
}

// round 5
// speedup vs baseline: 4.0612x; 1.0871x over previous
#include <cuda_runtime.h>
#include <math.h>
#include <stdint.h>

// Problem constants
#define D_MODEL 2048
#define SEQ     2048
#define BATCH   2
#define NHEAD   16
#define KVHEAD  4
#define HDIM    128
#define FF      5632
#define MTOT    (BATCH * SEQ)      // 4096
#define KD      (KVHEAD * HDIM)    // 512
#define QKV_N   3072               // 2048 q + 512 k + 512 v
#define VOFF    2560               // v column offset in fused qkv

// ---------------------------------------------------------------------------
// Scratch (no cudaMalloc allowed)
// ---------------------------------------------------------------------------
__device__ float g_h  [MTOT * (size_t)D_MODEL];   // rms1 out (perm), then attn out (perm)
__device__ float g_q  [MTOT * (size_t)D_MODEL];   // h2 (perm)
__device__ float g_qkv[MTOT * (size_t)QKV_N];     // fused q|k|v (v cols perm)
__device__ float g_act[MTOT * (size_t)FF];        // gate (perm), then swiglu (perm)
// rna-rounded, K-permuted weight copies
__device__ float w_qkv[(size_t)QKV_N * D_MODEL];
__device__ float w_o  [(size_t)D_MODEL * D_MODEL];
__device__ float w_g  [(size_t)FF * D_MODEL];
__device__ float w_u  [(size_t)FF * D_MODEL];
__device__ float w_d  [(size_t)D_MODEL * FF];
__device__ float b_qkv[QKV_N];                    // concat bias (unpermuted labels)

__device__ __forceinline__ uint32_t f2tf32(float x) {
    uint32_t u;
    asm("cvt.rna.tf32.f32 %0, %1;" : "=r"(u) : "f"(x));
    return u;
}
__device__ __forceinline__ float rnatf(float x) {
    return __uint_as_float(f2tf32(x));
}

#define MMA_TF32(d, a, b)                                                   \
    asm volatile(                                                           \
        "mma.sync.aligned.m16n8k8.row.col.f32.tf32.tf32.f32 "               \
        "{%0,%1,%2,%3}, {%4,%5,%6,%7}, {%8,%9}, {%0,%1,%2,%3};"             \
        : "+f"(d[0]), "+f"(d[1]), "+f"(d[2]), "+f"(d[3])                    \
        : "r"(a[0]), "r"(a[1]), "r"(a[2]), "r"(a[3]), "r"(b[0]), "r"(b[1]))

__device__ __forceinline__ void cp_async16(void* dst, const void* src) {
    uint32_t s = (uint32_t)__cvta_generic_to_shared(dst);
    asm volatile("cp.async.cg.shared.global [%0], [%1], 16;\n" :: "r"(s), "l"(src));
}
__device__ __forceinline__ void cp_commit() {
    asm volatile("cp.async.commit_group;\n");
}
template<int N> __device__ __forceinline__ void cp_wait() {
    asm volatile("cp.async.wait_group %0;\n" :: "n"(N));
}

// K-permutation within 8-groups: position p(k) = (k&3)*2 + (k>>2).
// Storage order per group: [a0,a4,a1,a5,a2,a6,a3,a7].

// ---------------------------------------------------------------------------
// cvt: rna-round + K-permute all weights; pack w_qkv; concat biases.
// One thread = one 8-float group.
// ---------------------------------------------------------------------------
#define NSEG 10
struct CvtArgs {
    const float* s[NSEG];
    float* d[NSEG];
    int end[NSEG];      // exclusive prefix end, in 8-float groups
    int perm;           // bitmask: segment gets permuted store
};

__global__ void __launch_bounds__(256) cvt_all_kernel(CvtArgs a, int totalg)
{
    const int i = blockIdx.x * 256 + threadIdx.x;
    if (i >= totalg) return;
    int j = 0;
    #pragma unroll
    for (int t = 0; t < NSEG - 1; ++t)
        if (i >= a.end[t]) j = t + 1;
    const int gi = i - (j ? a.end[j - 1] : 0);
    const float4* s = (const float4*)a.s[j];
    float4* d = (float4*)a.d[j];
    float4 lo = s[gi * 2], hi = s[gi * 2 + 1];
    lo.x = rnatf(lo.x); lo.y = rnatf(lo.y); lo.z = rnatf(lo.z); lo.w = rnatf(lo.w);
    hi.x = rnatf(hi.x); hi.y = rnatf(hi.y); hi.z = rnatf(hi.z); hi.w = rnatf(hi.w);
    if ((a.perm >> j) & 1) {
        float4 o0; o0.x = lo.x; o0.y = hi.x; o0.z = lo.y; o0.w = hi.y;
        float4 o1; o1.x = lo.z; o1.y = hi.z; o1.z = lo.w; o1.w = hi.w;
        d[gi * 2] = o0; d[gi * 2 + 1] = o1;
    } else {
        d[gi * 2] = lo; d[gi * 2 + 1] = hi;
    }
}

// ---------------------------------------------------------------------------
// RMSNorm, permuted + rna-rounded output. Thread t owns cols 8t..8t+7.
// ---------------------------------------------------------------------------
__global__ void __launch_bounds__(256) rmsnorm_kernel(
    const float* __restrict__ x, const float* __restrict__ w,
    float* __restrict__ o)
{
    const int row = blockIdx.x;
    const float* xr = x + (size_t)row * D_MODEL;
    float* orow     = o + (size_t)row * D_MODEL;
    const int t = threadIdx.x;

    float4 a = *(const float4*)(xr + 8 * t);
    float4 b = *(const float4*)(xr + 8 * t + 4);
    float ss = a.x*a.x + a.y*a.y + a.z*a.z + a.w*a.w
             + b.x*b.x + b.y*b.y + b.z*b.z + b.w*b.w;
    #pragma unroll
    for (int off = 16; off; off >>= 1)
        ss += __shfl_xor_sync(0xffffffffu, ss, off);
    __shared__ float warp_s[8];
    if ((t & 31) == 0) warp_s[t >> 5] = ss;
    __syncthreads();
    float tot = 0.f;
    #pragma unroll
    for (int i = 0; i < 8; ++i) tot += warp_s[i];
    const float inv = rsqrtf(tot * (1.0f / D_MODEL) + 1e-6f);

    float4 w1 = *(const float4*)(w + 8 * t);
    float4 w2 = *(const float4*)(w + 8 * t + 4);
    float n0 = rnatf(a.x * inv * w1.x), n1 = rnatf(a.y * inv * w1.y);
    float n2 = rnatf(a.z * inv * w1.z), n3 = rnatf(a.w * inv * w1.w);
    float n4 = rnatf(b.x * inv * w2.x), n5 = rnatf(b.y * inv * w2.y);
    float n6 = rnatf(b.z * inv * w2.z), n7 = rnatf(b.w * inv * w2.w);
    float4 o0; o0.x = n0; o0.y = n4; o0.z = n1; o0.w = n5;   // permuted
    float4 o1; o1.x = n2; o1.y = n6; o1.z = n3; o1.w = n7;
    *(float4*)(orow + 8 * t)     = o0;
    *(float4*)(orow + 8 * t + 4) = o1;
}

// ---------------------------------------------------------------------------
// TF32 GEMM, 2-stage cp.async, LDS.64 fragment loads (K-permuted operands).
// C[M,N] = A[M,K] @ W[N,K]^T (+ epilogue).
//   EPI 0: +bias[col label]   EPI 1: +aux[row,pos]   EPI 2: silu(aux)*acc
//   CVT 1: rna-round output
//   PERM 0: none   1: permute all output cols   2: permute only cols >= VOFF
// ---------------------------------------------------------------------------
#define BK 32
#define GSST 40                              // stride === 8 (mod 32): LDS.64 conflict-free
#define STAGE_F (2 * 128 * GSST)             // 10240 floats
#define GEMM_SMEM (2 * STAGE_F * 4)          // 81920 bytes

template<int EPI, int CVT, int PERM>
__global__ void __launch_bounds__(256, 2) gemm_tc(
    const float* __restrict__ A, const float* __restrict__ W,
    const float* aux, float* __restrict__ C,
    int M, int N, int K)
{
    extern __shared__ float sm[];
    const int tid  = threadIdx.x;
    const int warp = tid >> 5;
    const int lane = tid & 31;
    const int bm = blockIdx.y * 128;
    const int bn = blockIdx.x * 128;
    const int m_w = (warp >> 2) * 64;
    const int n_w = (warp & 3) * 32;
    const int lr4 = lane >> 2;
    const int lk  = lane & 3;

    const float* Ab = A + (size_t)bm * K;
    const float* Wb = W + (size_t)bn * K;

    float acc[4][4][4];
    #pragma unroll
    for (int mt = 0; mt < 4; ++mt)
        #pragma unroll
        for (int nt = 0; nt < 4; ++nt)
            #pragma unroll
            for (int r = 0; r < 4; ++r) acc[mt][nt][r] = 0.f;

    const int nk = K / BK;

    auto load_stage = [&](int st, int k0) {
        float* As = sm + st * STAGE_F;
        float* Bs = As + 128 * GSST;
        #pragma unroll
        for (int i = 0; i < 4; ++i) {
            const int idx = tid + i * 256;
            const int row = idx >> 3;
            const int c4  = (idx & 7) << 2;
            cp_async16(&As[row * GSST + c4], Ab + (size_t)row * K + k0 + c4);
            cp_async16(&Bs[row * GSST + c4], Wb + (size_t)row * K + k0 + c4);
        }
    };

    load_stage(0, 0);   cp_commit();
    if (nk > 1) load_stage(1, BK);
    cp_commit();

    for (int kt = 0; kt < nk; ++kt) {
        cp_wait<1>();
        __syncthreads();

        const uint32_t* As = (const uint32_t*)(sm + (kt & 1) * STAGE_F);
        const uint32_t* Bs = As + 128 * GSST;
        #pragma unroll
        for (int kk = 0; kk < 4; ++kk) {
            const int k0 = kk * 8;
            uint32_t afr[4][4], bfr[4][2];
            #pragma unroll
            for (int mt = 0; mt < 4; ++mt) {
                const int r = m_w + mt * 16 + lr4;
                const uint2 lo = *(const uint2*)&As[r * GSST + k0 + 2 * lk];
                const uint2 hi = *(const uint2*)&As[(r + 8) * GSST + k0 + 2 * lk];
                afr[mt][0] = lo.x; afr[mt][2] = lo.y;
                afr[mt][1] = hi.x; afr[mt][3] = hi.y;
            }
            #pragma unroll
            for (int nt = 0; nt < 4; ++nt) {
                const int rn = n_w + nt * 8 + lr4;
                const uint2 bb = *(const uint2*)&Bs[rn * GSST + k0 + 2 * lk];
                bfr[nt][0] = bb.x; bfr[nt][1] = bb.y;
            }
            #pragma unroll
            for (int mt = 0; mt < 4; ++mt)
                #pragma unroll
                for (int nt = 0; nt < 4; ++nt)
                    MMA_TF32(acc[mt][nt], afr[mt], bfr[nt]);
        }
        __syncthreads();
        if (kt + 2 < nk) load_stage(kt & 1, (kt + 2) * BK);
        cp_commit();
    }

    // ---- epilogue ----
    #pragma unroll
    for (int mt = 0; mt < 4; ++mt) {
        #pragma unroll
        for (int half = 0; half < 2; ++half) {
            const int row = bm + m_w + mt * 16 + lr4 + half * 8;
            const size_t base = (size_t)row * N;
            #pragma unroll
            for (int nt = 0; nt < 4; ++nt) {
                const int col = bn + n_w + nt * 8 + 2 * lk;   // label
                float v0 = acc[mt][nt][half * 2 + 0];
                float v1 = acc[mt][nt][half * 2 + 1];

                int p0 = col, p1 = col + 1;
                bool dop = false;
                if (PERM == 1) dop = true;
                if (PERM == 2) dop = (col >= VOFF);
                if (dop) {
                    const int gg = col & ~7, k = col & 7;
                    p0 = gg + (k & 3) * 2 + (k >> 2);
                    p1 = gg + ((k + 1) & 3) * 2 + ((k + 1) >> 2);
                }

                if (EPI == 0) {
                    if (aux) { v0 += aux[col]; v1 += aux[col + 1]; }
                } else if (EPI == 1) {
                    v0 += aux[base + p0]; v1 += aux[base + p1];
                } else {
                    const float ga = aux[base + p0];
                    const float gb = aux[base + p1];
                    v0 *= ga / (1.0f + __expf(-ga));
                    v1 *= gb / (1.0f + __expf(-gb));
                }
                if (CVT) { v0 = rnatf(v0); v1 = rnatf(v1); }

                if (PERM == 0) {
                    float2 r; r.x = v0; r.y = v1;
                    *(float2*)(C + base + p0) = r;
                } else {
                    C[base + p0] = v0;
                    C[base + p1] = v1;
                }
            }
        }
    }
}

// ---------------------------------------------------------------------------
// Flash attention (unchanged math; reads fused qkv buffer, stride 3072).
// ---------------------------------------------------------------------------
#define FQT 128
#define FKT 64
#define KST 132
#define VST 136
#define PST 68
#define KV_STAGE (FKT * KST + FKT * VST)
#define FLASH_SMEM ((2 * KV_STAGE + FQT * PST) * 4)

__global__ void __launch_bounds__(256) flash_tc_kernel(
    const float* __restrict__ qkv, float* __restrict__ Ob)
{
    extern __shared__ float fs[];
    float* S0 = fs;
    float* S1 = fs + KV_STAGE;
    float* Ps = fs + 2 * KV_STAGE;

    const int bx   = blockIdx.x;
    const int hh   = blockIdx.y;
    const int b    = blockIdx.z;
    const int g    = hh & (KVHEAD - 1);
    const int tid  = threadIdx.x;
    const int warp = tid >> 5;
    const int lane = tid & 31;
    const int lr   = lane >> 2;
    const int lq   = lane & 3;
    const int mb   = warp * 16;
    const int qbase = bx * FQT;
    const float scale = 0.08838834764831845f;

    // stage Q (cols 0..2047 of qkv), extract fragments
    const float* qptr = qkv + ((size_t)b * SEQ + qbase) * QKV_N + hh * HDIM;
    #pragma unroll
    for (int it = 0; it < 16; ++it) {
        const int idx = tid + it * 256;
        const int row = idx >> 5;
        const int c4  = (idx & 31) << 2;
        float4 v = *(const float4*)(qptr + (size_t)row * QKV_N + c4);
        float* d = &S0[row * KST + c4];
        d[0] = v.x * scale; d[1] = v.y * scale;
        d[2] = v.z * scale; d[3] = v.w * scale;
    }
    __syncthreads();
    uint32_t qf[16][4];
    #pragma unroll
    for (int kk = 0; kk < 16; ++kk) {
        const int k0 = kk * 8;
        qf[kk][0] = __float_as_uint(S0[(mb + lr)     * KST + k0 + lq]);
        qf[kk][1] = __float_as_uint(S0[(mb + lr + 8) * KST + k0 + lq]);
        qf[kk][2] = __float_as_uint(S0[(mb + lr)     * KST + k0 + lq + 4]);
        qf[kk][3] = __float_as_uint(S0[(mb + lr + 8) * KST + k0 + lq + 4]);
    }
    __syncthreads();

    const int nkt = 2 * (bx + 1);

    auto load_kv = [&](float* St, int ktb) {
        const float* kptr = qkv + ((size_t)b * SEQ + ktb) * QKV_N + D_MODEL + g * HDIM;
        const float* vptr = qkv + ((size_t)b * SEQ + ktb) * QKV_N + VOFF    + g * HDIM;
        float* Kd = St;
        float* Vd = St + FKT * KST;
        #pragma unroll
        for (int it = 0; it < 8; ++it) {
            const int idx = tid + it * 256;
            const int row = idx >> 5;
            const int c4  = (idx & 31) << 2;
            cp_async16(&Kd[row * KST + c4], kptr + (size_t)row * QKV_N + c4);
            cp_async16(&Vd[row * VST + c4], vptr + (size_t)row * QKV_N + c4);
        }
    };

    load_kv(S0, 0);
    cp_commit();
    if (nkt > 1) load_kv(S1, FKT);
    cp_commit();

    float o[16][4];
    #pragma unroll
    for (int nt = 0; nt < 16; ++nt)
        o[nt][0] = o[nt][1] = o[nt][2] = o[nt][3] = 0.f;
    float m0 = -1e30f, m1 = -1e30f, l0 = 0.f, l1 = 0.f;
    const int r0g = qbase + mb + lr;
    const int r1g = r0g + 8;

    for (int kt = 0; kt < nkt; ++kt) {
        cp_wait<1>();
        __syncthreads();
        const float* St = (kt & 1) ? S1 : S0;
        const float* Ks = St;
        const float* Vs = St + FKT * KST;
        const int ktb = kt * FKT;

        float s[8][4];
        #pragma unroll
        for (int nt = 0; nt < 8; ++nt)
            s[nt][0] = s[nt][1] = s[nt][2] = s[nt][3] = 0.f;
        #pragma unroll
        for (int kk = 0; kk < 16; ++kk) {
            const int k0 = kk * 8;
            #pragma unroll
            for (int nt = 0; nt < 8; ++nt) {
                uint32_t bfr[2];
                bfr[0] = __float_as_uint(Ks[(nt * 8 + lr) * KST + k0 + lq]);
                bfr[1] = __float_as_uint(Ks[(nt * 8 + lr) * KST + k0 + lq + 4]);
                MMA_TF32(s[nt], qf[kk], bfr);
            }
        }

        float mx0 = -1e30f, mx1 = -1e30f;
        #pragma unroll
        for (int nt = 0; nt < 8; ++nt) {
            const int c = ktb + nt * 8 + 2 * lq;
            if (c     > r0g) s[nt][0] = -1e30f;
            if (c + 1 > r0g) s[nt][1] = -1e30f;
            if (c     > r1g) s[nt][2] = -1e30f;
            if (c + 1 > r1g) s[nt][3] = -1e30f;
            mx0 = fmaxf(mx0, fmaxf(s[nt][0], s[nt][1]));
            mx1 = fmaxf(mx1, fmaxf(s[nt][2], s[nt][3]));
        }
        mx0 = fmaxf(mx0, __shfl_xor_sync(0xffffffffu, mx0, 1));
        mx0 = fmaxf(mx0, __shfl_xor_sync(0xffffffffu, mx0, 2));
        mx1 = fmaxf(mx1, __shfl_xor_sync(0xffffffffu, mx1, 1));
        mx1 = fmaxf(mx1, __shfl_xor_sync(0xffffffffu, mx1, 2));
        const float mn0 = fmaxf(m0, mx0), mn1 = fmaxf(m1, mx1);
        const float al0 = __expf(m0 - mn0), al1 = __expf(m1 - mn1);
        m0 = mn0; m1 = mn1;

        float ps0 = 0.f, ps1 = 0.f;
        #pragma unroll
        for (int nt = 0; nt < 8; ++nt) {
            const float p0 = __expf(s[nt][0] - mn0);
            const float p1 = __expf(s[nt][1] - mn0);
            const float p2 = __expf(s[nt][2] - mn1);
            const float p3 = __expf(s[nt][3] - mn1);
            ps0 += p0 + p1; ps1 += p2 + p3;
            float2 lo; lo.x = p0; lo.y = p1;
            float2 hi; hi.x = p2; hi.y = p3;
            *(float2*)&Ps[(mb + lr)     * PST + nt * 8 + 2 * lq] = lo;
            *(float2*)&Ps[(mb + lr + 8) * PST + nt * 8 + 2 * lq] = hi;
        }
        ps0 += __shfl_xor_sync(0xffffffffu, ps0, 1);
        ps0 += __shfl_xor_sync(0xffffffffu, ps0, 2);
        ps1 += __shfl_xor_sync(0xffffffffu, ps1, 1);
        ps1 += __shfl_xor_sync(0xffffffffu, ps1, 2);
        l0 = l0 * al0 + ps0;
        l1 = l1 * al1 + ps1;

        #pragma unroll
        for (int nt = 0; nt < 16; ++nt) {
            o[nt][0] *= al0; o[nt][1] *= al0;
            o[nt][2] *= al1; o[nt][3] *= al1;
        }
        __syncwarp();

        #pragma unroll
        for (int kk = 0; kk < 8; ++kk) {
            const int k0 = kk * 8;
            uint32_t a[4];
            a[0] = __float_as_uint(Ps[(mb + lr)     * PST + k0 + lq]);
            a[1] = __float_as_uint(Ps[(mb + lr + 8) * PST + k0 + lq]);
            a[2] = __float_as_uint(Ps[(mb + lr)     * PST + k0 + lq + 4]);
            a[3] = __float_as_uint(Ps[(mb + lr + 8) * PST + k0 + lq + 4]);
            #pragma unroll
            for (int nt = 0; nt < 16; ++nt) {
                uint32_t bfr[2];
                bfr[0] = __float_as_uint(Vs[(k0 + lq)     * VST + nt * 8 + lr]);
                bfr[1] = __float_as_uint(Vs[(k0 + lq + 4) * VST + nt * 8 + lr]);
                MMA_TF32(o[nt], a, bfr);
            }
        }
        __syncthreads();

        const int nx = kt + 2;
        if (nx < nkt) load_kv((nx & 1) ? S1 : S0, nx * FKT);
        cp_commit();
    }

    const float i0 = 1.0f / l0, i1 = 1.0f / l1;
    float* op = Ob + ((size_t)b * SEQ + qbase + mb) * D_MODEL + hh * HDIM;
    #pragma unroll
    for (int nt = 0; nt < 16; ++nt) {
        const int col = nt * 8 + 2 * lq;
        float2 lo; lo.x = rnatf(o[nt][0] * i0); lo.y = rnatf(o[nt][1] * i0);
        float2 hi; hi.x = rnatf(o[nt][2] * i1); hi.y = rnatf(o[nt][3] * i1);
        *(float2*)(op + (size_t)lr * D_MODEL + col)       = lo;
        *(float2*)(op + (size_t)(lr + 8) * D_MODEL + col) = hi;
    }
}

// ---------------------------------------------------------------------------
// Launch sequence
// ---------------------------------------------------------------------------
extern "C" void kernel_launch(void* const* d_in, const int* in_sizes, int n_in,
                              void* d_out, int out_size)
{
    const float* x      = (const float*)d_in[0];
    const float* ln1_w  = (const float*)d_in[1];
    const float* q_w    = (const float*)d_in[2];
    const float* q_b    = (const float*)d_in[3];
    const float* k_w    = (const float*)d_in[4];
    const float* k_b    = (const float*)d_in[5];
    const float* v_w    = (const float*)d_in[6];
    const float* v_b    = (const float*)d_in[7];
    const float* o_w    = (const float*)d_in[8];
    const float* ln2_w  = (const float*)d_in[9];
    const float* gate_w = (const float*)d_in[10];
    const float* up_w   = (const float*)d_in[11];
    const float* down_w = (const float*)d_in[12];
    float* out = (float*)d_out;

    float *h, *hq, *qkv, *act;
    float *wqkv, *wo, *wg, *wu, *wd, *bqkv;
    cudaGetSymbolAddress((void**)&h,    g_h);
    cudaGetSymbolAddress((void**)&hq,   g_q);
    cudaGetSymbolAddress((void**)&qkv,  g_qkv);
    cudaGetSymbolAddress((void**)&act,  g_act);
    cudaGetSymbolAddress((void**)&wqkv, w_qkv);
    cudaGetSymbolAddress((void**)&wo,   w_o);
    cudaGetSymbolAddress((void**)&wg,   w_g);
    cudaGetSymbolAddress((void**)&wu,   w_u);
    cudaGetSymbolAddress((void**)&wd,   w_d);
    cudaGetSymbolAddress((void**)&bqkv, b_qkv);

    cudaFuncSetAttribute(gemm_tc<0,0,2>, cudaFuncAttributeMaxDynamicSharedMemorySize, GEMM_SMEM);
    cudaFuncSetAttribute(gemm_tc<1,0,0>, cudaFuncAttributeMaxDynamicSharedMemorySize, GEMM_SMEM);
    cudaFuncSetAttribute(gemm_tc<0,0,1>, cudaFuncAttributeMaxDynamicSharedMemorySize, GEMM_SMEM);
    cudaFuncSetAttribute(gemm_tc<2,1,1>, cudaFuncAttributeMaxDynamicSharedMemorySize, GEMM_SMEM);
    cudaFuncSetAttribute(flash_tc_kernel, cudaFuncAttributeMaxDynamicSharedMemorySize, FLASH_SMEM);

    // 0. round + permute weights, pack qkv, concat biases (single launch)
    {
        CvtArgs a;
        const float* srcs[NSEG] = { q_w, k_w, v_w, o_w, gate_w, up_w, down_w,
                                    q_b, k_b, v_b };
        float* dsts[NSEG] = { wqkv,
                              wqkv + (size_t)D_MODEL * D_MODEL,
                              wqkv + (size_t)VOFF * D_MODEL,
                              wo, wg, wu, wd,
                              bqkv, bqkv + D_MODEL, bqkv + VOFF };
        const long long n[NSEG] = {
            (long long)D_MODEL*D_MODEL, (long long)KD*D_MODEL, (long long)KD*D_MODEL,
            (long long)D_MODEL*D_MODEL, (long long)FF*D_MODEL, (long long)FF*D_MODEL,
            (long long)D_MODEL*FF, D_MODEL, KD, KD };
        int accg = 0;
        for (int i = 0; i < NSEG; ++i) {
            a.s[i] = srcs[i]; a.d[i] = dsts[i];
            accg += (int)(n[i] / 8); a.end[i] = accg;
        }
        a.perm = 0x7F;   // segments 0-6 (weights) permuted, biases not
        cvt_all_kernel<<<(accg + 255) / 256, 256>>>(a, accg);
    }

    // 1. h = rmsnorm(x, ln1)  [permuted]
    rmsnorm_kernel<<<MTOT, 256>>>(x, ln1_w, h);

    // 2. fused qkv projection (v columns permuted in epilogue)
    gemm_tc<0,0,2><<<dim3(QKV_N/128, MTOT/128), 256, GEMM_SMEM>>>(h, wqkv, bqkv, qkv, MTOT, QKV_N, D_MODEL);

    // 3. flash attention -> h (columns inherit v permutation)
    flash_tc_kernel<<<dim3(SEQ/FQT, NHEAD, BATCH), 256, FLASH_SMEM>>>(qkv, h);

    // 4. x1 = x + attn @ o_w^T -> d_out (unpermuted)
    gemm_tc<1,0,0><<<dim3(D_MODEL/128, MTOT/128), 256, GEMM_SMEM>>>(h, wo, x, out, MTOT, D_MODEL, D_MODEL);

    // 5. h2 = rmsnorm(x1, ln2) -> hq  [permuted]
    rmsnorm_kernel<<<MTOT, 256>>>(out, ln2_w, hq);

    // 6. gate = h2 @ gate_w^T  [permuted]
    gemm_tc<0,0,1><<<dim3(FF/128, MTOT/128), 256, GEMM_SMEM>>>(hq, wg, (const float*)nullptr, act, MTOT, FF, D_MODEL);

    // 7. act = silu(gate) * (h2 @ up_w^T)  [permuted, rounded]
    gemm_tc<2,1,1><<<dim3(FF/128, MTOT/128), 256, GEMM_SMEM>>>(hq, wu, act, act, MTOT, FF, D_MODEL);

    // 8. out = x1 + act @ down_w^T (unpermuted)
    gemm_tc<1,0,0><<<dim3(D_MODEL/128, MTOT/128), 256, GEMM_SMEM>>>(act, wd, out, out, MTOT, D_MODEL, FF);
}

// round 7
// speedup vs baseline: 7.0100x; 1.7261x over previous
#include <cuda_runtime.h>
#include <cuda_fp16.h>
#include <math.h>
#include <stdint.h>

// Problem constants
#define D_MODEL 2048
#define SEQ     2048
#define BATCH   2
#define NHEAD   16
#define KVHEAD  4
#define HDIM    128
#define FF      5632
#define MTOT    (BATCH * SEQ)      // 4096
#define KD      (KVHEAD * HDIM)    // 512
#define QKV_N   3072
#define VOFF    2560

// ---------------------------------------------------------------------------
// Scratch (no cudaMalloc allowed)
// ---------------------------------------------------------------------------
__device__ __half g_h  [MTOT * (size_t)D_MODEL];   // rms1 out, then attn out (half, pair-perm)
__device__ __half g_h2 [MTOT * (size_t)D_MODEL];   // rms2 out (half, pair-perm)
__device__ float  g_qkv[MTOT * (size_t)QKV_N];     // fused q|k|v (fp32, plain)
__device__ float  g_gate[MTOT * (size_t)FF];       // gate (fp32, plain)
__device__ __half g_act[MTOT * (size_t)FF];        // swiglu (half, pair-perm)
// fp16 pair-permuted weights
__device__ __half w_qkvh[(size_t)QKV_N * D_MODEL];
__device__ __half w_oh  [(size_t)D_MODEL * D_MODEL];
__device__ __half w_gh  [(size_t)FF * D_MODEL];
__device__ __half w_uh  [(size_t)FF * D_MODEL];
__device__ __half w_dh  [(size_t)D_MODEL * FF];
__device__ float  b_qkv [QKV_N];

// Pair-permutation on 16-element K-groups: pair j=(k>>1)&7 stored at word
// position p(j) = (j&3)*2 + (j>>2). Gives LDS.64 fragments AND half2 stores.
__device__ __forceinline__ int ppos(int col) {   // half-index of pair start
    const int j = (col >> 1) & 7;
    return (col & ~15) + 2 * ((j & 3) * 2 + (j >> 2));
}

#define MMA_F16(d, a, b)                                                    \
    asm volatile(                                                           \
        "mma.sync.aligned.m16n8k16.row.col.f32.f16.f16.f32 "                \
        "{%0,%1,%2,%3}, {%4,%5,%6,%7}, {%8,%9}, {%0,%1,%2,%3};"             \
        : "+f"(d[0]), "+f"(d[1]), "+f"(d[2]), "+f"(d[3])                    \
        : "r"(a[0]), "r"(a[1]), "r"(a[2]), "r"(a[3]), "r"(b[0]), "r"(b[1]))

#define MMA_TF32(d, a, b)                                                   \
    asm volatile(                                                           \
        "mma.sync.aligned.m16n8k8.row.col.f32.tf32.tf32.f32 "               \
        "{%0,%1,%2,%3}, {%4,%5,%6,%7}, {%8,%9}, {%0,%1,%2,%3};"             \
        : "+f"(d[0]), "+f"(d[1]), "+f"(d[2]), "+f"(d[3])                    \
        : "r"(a[0]), "r"(a[1]), "r"(a[2]), "r"(a[3]), "r"(b[0]), "r"(b[1]))

__device__ __forceinline__ void cp_async16(void* dst, const void* src) {
    uint32_t s = (uint32_t)__cvta_generic_to_shared(dst);
    asm volatile("cp.async.cg.shared.global [%0], [%1], 16;\n" :: "r"(s), "l"(src));
}
__device__ __forceinline__ void cp_commit() {
    asm volatile("cp.async.commit_group;\n");
}
template<int N> __device__ __forceinline__ void cp_wait() {
    asm volatile("cp.async.wait_group %0;\n" :: "n"(N));
}

// ---------------------------------------------------------------------------
// cvt: fp32 weights -> fp16 pair-permuted; biases -> fp32 concat copy.
// One thread = one 16-float group.
// ---------------------------------------------------------------------------
#define NSEG 10
struct CvtArgs {
    const float* s[NSEG];
    void* d[NSEG];
    int end[NSEG];
    int perm;        // bit set: half+perm output; clear: fp32 copy
};

__global__ void __launch_bounds__(256) cvt_all_kernel(CvtArgs a, int totalg)
{
    const int i = blockIdx.x * 256 + threadIdx.x;
    if (i >= totalg) return;
    int j = 0;
    #pragma unroll
    for (int t = 0; t < NSEG - 1; ++t)
        if (i >= a.end[t]) j = t + 1;
    const int gi = i - (j ? a.end[j - 1] : 0);
    const float4* s = (const float4*)a.s[j] + gi * 4;
    float4 f0 = s[0], f1 = s[1], f2 = s[2], f3 = s[3];
    if ((a.perm >> j) & 1) {
        float n[16] = { f0.x,f0.y,f0.z,f0.w, f1.x,f1.y,f1.z,f1.w,
                        f2.x,f2.y,f2.z,f2.w, f3.x,f3.y,f3.z,f3.w };
        uint32_t w[8];
        #pragma unroll
        for (int p = 0; p < 8; ++p) {
            const int pp = (p & 3) * 2 + (p >> 2);
            __half2 h = __floats2half2_rn(n[2 * p], n[2 * p + 1]);
            w[pp] = *(uint32_t*)&h;
        }
        uint4* d = (uint4*)a.d[j] + gi * 2;
        uint4 o0; o0.x = w[0]; o0.y = w[1]; o0.z = w[2]; o0.w = w[3];
        uint4 o1; o1.x = w[4]; o1.y = w[5]; o1.z = w[6]; o1.w = w[7];
        d[0] = o0; d[1] = o1;
    } else {
        float4* d = (float4*)a.d[j] + gi * 4;
        d[0] = f0; d[1] = f1; d[2] = f2; d[3] = f3;
    }
}

// ---------------------------------------------------------------------------
// RMSNorm: fp32 in -> half pair-permuted out. 128 threads, 16 cols/thread.
// ---------------------------------------------------------------------------
__global__ void __launch_bounds__(128) rmsnorm_kernel(
    const float* __restrict__ x, const float* __restrict__ w,
    __half* __restrict__ o)
{
    const int row = blockIdx.x;
    const float* xr = x + (size_t)row * D_MODEL;
    const int t = threadIdx.x;
    const int c0 = 16 * t;

    float4 f0 = *(const float4*)(xr + c0);
    float4 f1 = *(const float4*)(xr + c0 + 4);
    float4 f2 = *(const float4*)(xr + c0 + 8);
    float4 f3 = *(const float4*)(xr + c0 + 12);
    float n[16] = { f0.x,f0.y,f0.z,f0.w, f1.x,f1.y,f1.z,f1.w,
                    f2.x,f2.y,f2.z,f2.w, f3.x,f3.y,f3.z,f3.w };
    float ss = 0.f;
    #pragma unroll
    for (int i = 0; i < 16; ++i) ss += n[i] * n[i];
    #pragma unroll
    for (int off = 16; off; off >>= 1)
        ss += __shfl_xor_sync(0xffffffffu, ss, off);
    __shared__ float warp_s[4];
    if ((t & 31) == 0) warp_s[t >> 5] = ss;
    __syncthreads();
    float tot = warp_s[0] + warp_s[1] + warp_s[2] + warp_s[3];
    const float inv = rsqrtf(tot * (1.0f / D_MODEL) + 1e-6f);

    float4 w0 = *(const float4*)(w + c0);
    float4 w1 = *(const float4*)(w + c0 + 4);
    float4 w2 = *(const float4*)(w + c0 + 8);
    float4 w3 = *(const float4*)(w + c0 + 12);
    float wv[16] = { w0.x,w0.y,w0.z,w0.w, w1.x,w1.y,w1.z,w1.w,
                     w2.x,w2.y,w2.z,w2.w, w3.x,w3.y,w3.z,w3.w };
    uint32_t wd[8];
    #pragma unroll
    for (int p = 0; p < 8; ++p) {
        const int pp = (p & 3) * 2 + (p >> 2);
        __half2 h = __floats2half2_rn(n[2 * p] * inv * wv[2 * p],
                                      n[2 * p + 1] * inv * wv[2 * p + 1]);
        wd[pp] = *(uint32_t*)&h;
    }
    uint4* d = (uint4*)(o + (size_t)row * D_MODEL + c0);
    uint4 o0; o0.x = wd[0]; o0.y = wd[1]; o0.z = wd[2]; o0.w = wd[3];
    uint4 o1; o1.x = wd[4]; o1.y = wd[5]; o1.z = wd[6]; o1.w = wd[7];
    d[0] = o0; d[1] = o1;
}

// ---------------------------------------------------------------------------
// FP16 GEMM, 2-stage cp.async, LDS.64 fragments (pair-permuted operands).
// C[M,N] = A[M,K] @ W[N,K]^T (+ epilogue).
//   EPI 0: +bias[col] (aux may be null)  EPI 1: +aux[row,col]  EPI 2: silu(aux)*acc
//   OUTH 0: fp32 plain float2 stores      OUTH 1: half2 pair-permuted stores
// BK = 64 halves (4 x k16 steps), stride 40 words, 2 CTAs/SM.
// ---------------------------------------------------------------------------
#define GSTW 40                               // words (uint32) per smem row
#define STAGE_W (2 * 128 * GSTW)              // 10240 words/stage
#define GEMM_SMEM (2 * STAGE_W * 4)           // 81920 bytes

template<int EPI, int OUTH>
__global__ void __launch_bounds__(256, 2) gemm_f16(
    const __half* __restrict__ A, const __half* __restrict__ W,
    const float* aux, void* __restrict__ Cv,
    int M, int N, int K)
{
    extern __shared__ uint32_t smw[];
    const int tid  = threadIdx.x;
    const int warp = tid >> 5;
    const int lane = tid & 31;
    const int bm = blockIdx.y * 128;
    const int bn = blockIdx.x * 128;
    const int m_w = (warp >> 2) * 64;
    const int n_w = (warp & 3) * 32;
    const int lr4 = lane >> 2;
    const int lk  = lane & 3;

    const __half* Ab = A + (size_t)bm * K;
    const __half* Wb = W + (size_t)bn * K;

    float acc[4][4][4];
    #pragma unroll
    for (int mt = 0; mt < 4; ++mt)
        #pragma unroll
        for (int nt = 0; nt < 4; ++nt)
            #pragma unroll
            for (int r = 0; r < 4; ++r) acc[mt][nt][r] = 0.f;

    const int nk = K / 64;

    auto load_stage = [&](int st, int k0) {   // k0 in halves
        uint32_t* Aw = smw + st * STAGE_W;
        uint32_t* Bw = Aw + 128 * GSTW;
        #pragma unroll
        for (int i = 0; i < 4; ++i) {
            const int idx = tid + i * 256;
            const int row = idx >> 3;
            const int ch  = idx & 7;
            cp_async16(&Aw[row * GSTW + ch * 4], Ab + (size_t)row * K + k0 + ch * 8);
            cp_async16(&Bw[row * GSTW + ch * 4], Wb + (size_t)row * K + k0 + ch * 8);
        }
    };

    load_stage(0, 0);   cp_commit();
    if (nk > 1) load_stage(1, 64);
    cp_commit();

    for (int kt = 0; kt < nk; ++kt) {
        cp_wait<1>();
        __syncthreads();

        const uint32_t* As = smw + (kt & 1) * STAGE_W;
        const uint32_t* Bs = As + 128 * GSTW;
        #pragma unroll
        for (int kk = 0; kk < 4; ++kk) {
            const int k0 = kk * 8;
            uint32_t afr[4][4], bfr[4][2];
            #pragma unroll
            for (int mt = 0; mt < 4; ++mt) {
                const int r = m_w + mt * 16 + lr4;
                const uint2 lo = *(const uint2*)&As[r * GSTW + k0 + 2 * lk];
                const uint2 hi = *(const uint2*)&As[(r + 8) * GSTW + k0 + 2 * lk];
                afr[mt][0] = lo.x; afr[mt][2] = lo.y;
                afr[mt][1] = hi.x; afr[mt][3] = hi.y;
            }
            #pragma unroll
            for (int nt = 0; nt < 4; ++nt) {
                const int rn = n_w + nt * 8 + lr4;
                const uint2 bb = *(const uint2*)&Bs[rn * GSTW + k0 + 2 * lk];
                bfr[nt][0] = bb.x; bfr[nt][1] = bb.y;
            }
            #pragma unroll
            for (int mt = 0; mt < 4; ++mt)
                #pragma unroll
                for (int nt = 0; nt < 4; ++nt)
                    MMA_F16(acc[mt][nt], afr[mt], bfr[nt]);
        }
        __syncthreads();
        if (kt + 2 < nk) load_stage(kt & 1, (kt + 2) * 64);
        cp_commit();
    }

    // ---- epilogue ----
    #pragma unroll
    for (int mt = 0; mt < 4; ++mt) {
        #pragma unroll
        for (int half = 0; half < 2; ++half) {
            const int row = bm + m_w + mt * 16 + lr4 + half * 8;
            const size_t base = (size_t)row * N;
            #pragma unroll
            for (int nt = 0; nt < 4; ++nt) {
                const int col = bn + n_w + nt * 8 + 2 * lk;
                float v0 = acc[mt][nt][half * 2 + 0];
                float v1 = acc[mt][nt][half * 2 + 1];
                if (EPI == 0) {
                    if (aux) { v0 += aux[col]; v1 += aux[col + 1]; }
                } else if (EPI == 1) {
                    v0 += aux[base + col]; v1 += aux[base + col + 1];
                } else {
                    const float ga = aux[base + col];
                    const float gb = aux[base + col + 1];
                    v0 *= ga / (1.0f + __expf(-ga));
                    v1 *= gb / (1.0f + __expf(-gb));
                }
                if (OUTH) {
                    __half2 h = __floats2half2_rn(v0, v1);
                    *(__half2*)((__half*)Cv + base + ppos(col)) = h;
                } else {
                    float2 r; r.x = v0; r.y = v1;
                    *(float2*)((float*)Cv + base + col) = r;
                }
            }
        }
    }
}

// ---------------------------------------------------------------------------
// Flash attention (tf32 MMA, fp32 qkv input; half pair-permuted O output).
// Q-tile order reversed: heavy causal tiles launch first.
// ---------------------------------------------------------------------------
#define FQT 128
#define FKT 64
#define KST 132
#define VST 136
#define PST 68
#define KV_STAGE (FKT * KST + FKT * VST)
#define FLASH_SMEM ((2 * KV_STAGE + FQT * PST) * 4)

__global__ void __launch_bounds__(256) flash_tc_kernel(
    const float* __restrict__ qkv, __half* __restrict__ Ob)
{
    extern __shared__ float fs[];
    float* S0 = fs;
    float* S1 = fs + KV_STAGE;
    float* Ps = fs + 2 * KV_STAGE;

    const int bx   = (SEQ / FQT - 1) - blockIdx.x;   // reversed: heavy first
    const int hh   = blockIdx.y;
    const int b    = blockIdx.z;
    const int g    = hh & (KVHEAD - 1);
    const int tid  = threadIdx.x;
    const int warp = tid >> 5;
    const int lane = tid & 31;
    const int lr   = lane >> 2;
    const int lq   = lane & 3;
    const int mb   = warp * 16;
    const int qbase = bx * FQT;
    const float scale = 0.08838834764831845f;

    const float* qptr = qkv + ((size_t)b * SEQ + qbase) * QKV_N + hh * HDIM;
    #pragma unroll
    for (int it = 0; it < 16; ++it) {
        const int idx = tid + it * 256;
        const int row = idx >> 5;
        const int c4  = (idx & 31) << 2;
        float4 v = *(const float4*)(qptr + (size_t)row * QKV_N + c4);
        float* d = &S0[row * KST + c4];
        d[0] = v.x * scale; d[1] = v.y * scale;
        d[2] = v.z * scale; d[3] = v.w * scale;
    }
    __syncthreads();
    uint32_t qf[16][4];
    #pragma unroll
    for (int kk = 0; kk < 16; ++kk) {
        const int k0 = kk * 8;
        qf[kk][0] = __float_as_uint(S0[(mb + lr)     * KST + k0 + lq]);
        qf[kk][1] = __float_as_uint(S0[(mb + lr + 8) * KST + k0 + lq]);
        qf[kk][2] = __float_as_uint(S0[(mb + lr)     * KST + k0 + lq + 4]);
        qf[kk][3] = __float_as_uint(S0[(mb + lr + 8) * KST + k0 + lq + 4]);
    }
    __syncthreads();

    const int nkt = 2 * (bx + 1);

    auto load_kv = [&](float* St, int ktb) {
        const float* kptr = qkv + ((size_t)b * SEQ + ktb) * QKV_N + D_MODEL + g * HDIM;
        const float* vptr = qkv + ((size_t)b * SEQ + ktb) * QKV_N + VOFF    + g * HDIM;
        float* Kd = St;
        float* Vd = St + FKT * KST;
        #pragma unroll
        for (int it = 0; it < 8; ++it) {
            const int idx = tid + it * 256;
            const int row = idx >> 5;
            const int c4  = (idx & 31) << 2;
            cp_async16(&Kd[row * KST + c4], kptr + (size_t)row * QKV_N + c4);
            cp_async16(&Vd[row * VST + c4], vptr + (size_t)row * QKV_N + c4);
        }
    };

    load_kv(S0, 0);
    cp_commit();
    if (nkt > 1) load_kv(S1, FKT);
    cp_commit();

    float o[16][4];
    #pragma unroll
    for (int nt = 0; nt < 16; ++nt)
        o[nt][0] = o[nt][1] = o[nt][2] = o[nt][3] = 0.f;
    float m0 = -1e30f, m1 = -1e30f, l0 = 0.f, l1 = 0.f;
    const int r0g = qbase + mb + lr;
    const int r1g = r0g + 8;

    for (int kt = 0; kt < nkt; ++kt) {
        cp_wait<1>();
        __syncthreads();
        const float* St = (kt & 1) ? S1 : S0;
        const float* Ks = St;
        const float* Vs = St + FKT * KST;
        const int ktb = kt * FKT;

        float s[8][4];
        #pragma unroll
        for (int nt = 0; nt < 8; ++nt)
            s[nt][0] = s[nt][1] = s[nt][2] = s[nt][3] = 0.f;
        #pragma unroll
        for (int kk = 0; kk < 16; ++kk) {
            const int k0 = kk * 8;
            #pragma unroll
            for (int nt = 0; nt < 8; ++nt) {
                uint32_t bfr[2];
                bfr[0] = __float_as_uint(Ks[(nt * 8 + lr) * KST + k0 + lq]);
                bfr[1] = __float_as_uint(Ks[(nt * 8 + lr) * KST + k0 + lq + 4]);
                MMA_TF32(s[nt], qf[kk], bfr);
            }
        }

        float mx0 = -1e30f, mx1 = -1e30f;
        #pragma unroll
        for (int nt = 0; nt < 8; ++nt) {
            const int c = ktb + nt * 8 + 2 * lq;
            if (c     > r0g) s[nt][0] = -1e30f;
            if (c + 1 > r0g) s[nt][1] = -1e30f;
            if (c     > r1g) s[nt][2] = -1e30f;
            if (c + 1 > r1g) s[nt][3] = -1e30f;
            mx0 = fmaxf(mx0, fmaxf(s[nt][0], s[nt][1]));
            mx1 = fmaxf(mx1, fmaxf(s[nt][2], s[nt][3]));
        }
        mx0 = fmaxf(mx0, __shfl_xor_sync(0xffffffffu, mx0, 1));
        mx0 = fmaxf(mx0, __shfl_xor_sync(0xffffffffu, mx0, 2));
        mx1 = fmaxf(mx1, __shfl_xor_sync(0xffffffffu, mx1, 1));
        mx1 = fmaxf(mx1, __shfl_xor_sync(0xffffffffu, mx1, 2));
        const float mn0 = fmaxf(m0, mx0), mn1 = fmaxf(m1, mx1);
        const float al0 = __expf(m0 - mn0), al1 = __expf(m1 - mn1);
        m0 = mn0; m1 = mn1;

        float ps0 = 0.f, ps1 = 0.f;
        #pragma unroll
        for (int nt = 0; nt < 8; ++nt) {
            const float p0 = __expf(s[nt][0] - mn0);
            const float p1 = __expf(s[nt][1] - mn0);
            const float p2 = __expf(s[nt][2] - mn1);
            const float p3 = __expf(s[nt][3] - mn1);
            ps0 += p0 + p1; ps1 += p2 + p3;
            float2 lo; lo.x = p0; lo.y = p1;
            float2 hi; hi.x = p2; hi.y = p3;
            *(float2*)&Ps[(mb + lr)     * PST + nt * 8 + 2 * lq] = lo;
            *(float2*)&Ps[(mb + lr + 8) * PST + nt * 8 + 2 * lq] = hi;
        }
        ps0 += __shfl_xor_sync(0xffffffffu, ps0, 1);
        ps0 += __shfl_xor_sync(0xffffffffu, ps0, 2);
        ps1 += __shfl_xor_sync(0xffffffffu, ps1, 1);
        ps1 += __shfl_xor_sync(0xffffffffu, ps1, 2);
        l0 = l0 * al0 + ps0;
        l1 = l1 * al1 + ps1;

        #pragma unroll
        for (int nt = 0; nt < 16; ++nt) {
            o[nt][0] *= al0; o[nt][1] *= al0;
            o[nt][2] *= al1; o[nt][3] *= al1;
        }
        __syncwarp();

        #pragma unroll
        for (int kk = 0; kk < 8; ++kk) {
            const int k0 = kk * 8;
            uint32_t a[4];
            a[0] = __float_as_uint(Ps[(mb + lr)     * PST + k0 + lq]);
            a[1] = __float_as_uint(Ps[(mb + lr + 8) * PST + k0 + lq]);
            a[2] = __float_as_uint(Ps[(mb + lr)     * PST + k0 + lq + 4]);
            a[3] = __float_as_uint(Ps[(mb + lr + 8) * PST + k0 + lq + 4]);
            #pragma unroll
            for (int nt = 0; nt < 16; ++nt) {
                uint32_t bfr[2];
                bfr[0] = __float_as_uint(Vs[(k0 + lq)     * VST + nt * 8 + lr]);
                bfr[1] = __float_as_uint(Vs[(k0 + lq + 4) * VST + nt * 8 + lr]);
                MMA_TF32(o[nt], a, bfr);
            }
        }
        __syncthreads();

        const int nx = kt + 2;
        if (nx < nkt) load_kv((nx & 1) ? S1 : S0, nx * FKT);
        cp_commit();
    }

    // write O: half, pair-permuted (feeds o-proj fp16 GEMM)
    const float i0 = 1.0f / l0, i1 = 1.0f / l1;
    __half* op = Ob + ((size_t)b * SEQ + qbase + mb) * D_MODEL;
    #pragma unroll
    for (int nt = 0; nt < 16; ++nt) {
        const int label = hh * HDIM + nt * 8 + 2 * lq;
        const int pos = ppos(label);
        __half2 lo = __floats2half2_rn(o[nt][0] * i0, o[nt][1] * i0);
        __half2 hi = __floats2half2_rn(o[nt][2] * i1, o[nt][3] * i1);
        *(__half2*)(op + (size_t)lr * D_MODEL + pos)       = lo;
        *(__half2*)(op + (size_t)(lr + 8) * D_MODEL + pos) = hi;
    }
}

// ---------------------------------------------------------------------------
// Launch sequence
// ---------------------------------------------------------------------------
extern "C" void kernel_launch(void* const* d_in, const int* in_sizes, int n_in,
                              void* d_out, int out_size)
{
    const float* x      = (const float*)d_in[0];
    const float* ln1_w  = (const float*)d_in[1];
    const float* q_w    = (const float*)d_in[2];
    const float* q_b    = (const float*)d_in[3];
    const float* k_w    = (const float*)d_in[4];
    const float* k_b    = (const float*)d_in[5];
    const float* v_w    = (const float*)d_in[6];
    const float* v_b    = (const float*)d_in[7];
    const float* o_w    = (const float*)d_in[8];
    const float* ln2_w  = (const float*)d_in[9];
    const float* gate_w = (const float*)d_in[10];
    const float* up_w   = (const float*)d_in[11];
    const float* down_w = (const float*)d_in[12];
    float* out = (float*)d_out;

    __half *h, *h2, *act;
    float *qkv, *gate, *bq;
    __half *wqkv, *wo, *wg, *wu, *wd;
    cudaGetSymbolAddress((void**)&h,    g_h);
    cudaGetSymbolAddress((void**)&h2,   g_h2);
    cudaGetSymbolAddress((void**)&qkv,  g_qkv);
    cudaGetSymbolAddress((void**)&gate, g_gate);
    cudaGetSymbolAddress((void**)&act,  g_act);
    cudaGetSymbolAddress((void**)&wqkv, w_qkvh);
    cudaGetSymbolAddress((void**)&wo,   w_oh);
    cudaGetSymbolAddress((void**)&wg,   w_gh);
    cudaGetSymbolAddress((void**)&wu,   w_uh);
    cudaGetSymbolAddress((void**)&wd,   w_dh);
    cudaGetSymbolAddress((void**)&bq,   b_qkv);

    cudaFuncSetAttribute(gemm_f16<0,0>, cudaFuncAttributeMaxDynamicSharedMemorySize, GEMM_SMEM);
    cudaFuncSetAttribute(gemm_f16<1,0>, cudaFuncAttributeMaxDynamicSharedMemorySize, GEMM_SMEM);
    cudaFuncSetAttribute(gemm_f16<2,1>, cudaFuncAttributeMaxDynamicSharedMemorySize, GEMM_SMEM);
    cudaFuncSetAttribute(flash_tc_kernel, cudaFuncAttributeMaxDynamicSharedMemorySize, FLASH_SMEM);

    // 0. convert weights to fp16 pair-permuted; concat biases (one launch)
    {
        CvtArgs a;
        const float* srcs[NSEG] = { q_w, k_w, v_w, o_w, gate_w, up_w, down_w,
                                    q_b, k_b, v_b };
        void* dsts[NSEG] = { (void*)wqkv,
                             (void*)(wqkv + (size_t)D_MODEL * D_MODEL),
                             (void*)(wqkv + (size_t)VOFF * D_MODEL),
                             (void*)wo, (void*)wg, (void*)wu, (void*)wd,
                             (void*)bq, (void*)(bq + D_MODEL), (void*)(bq + VOFF) };
        const long long n[NSEG] = {
            (long long)D_MODEL*D_MODEL, (long long)KD*D_MODEL, (long long)KD*D_MODEL,
            (long long)D_MODEL*D_MODEL, (long long)FF*D_MODEL, (long long)FF*D_MODEL,
            (long long)D_MODEL*FF, D_MODEL, KD, KD };
        int accg = 0;
        for (int i = 0; i < NSEG; ++i) {
            a.s[i] = srcs[i]; a.d[i] = dsts[i];
            accg += (int)(n[i] / 16); a.end[i] = accg;
        }
        a.perm = 0x7F;
        cvt_all_kernel<<<(accg + 255) / 256, 256>>>(a, accg);
    }

    // 1. h = rmsnorm(x, ln1)  [half, perm]
    rmsnorm_kernel<<<MTOT, 128>>>(x, ln1_w, h);

    // 2. fused qkv projection -> fp32 plain (+bias)
    gemm_f16<0,0><<<dim3(QKV_N/128, MTOT/128), 256, GEMM_SMEM>>>(h, wqkv, bq, qkv, MTOT, QKV_N, D_MODEL);

    // 3. flash attention -> g_h (half, perm)
    flash_tc_kernel<<<dim3(SEQ/FQT, NHEAD, BATCH), 256, FLASH_SMEM>>>(qkv, h);

    // 4. x1 = x + attn @ o_w^T -> d_out (fp32)
    gemm_f16<1,0><<<dim3(D_MODEL/128, MTOT/128), 256, GEMM_SMEM>>>(h, wo, x, out, MTOT, D_MODEL, D_MODEL);

    // 5. h2 = rmsnorm(x1, ln2)  [half, perm]
    rmsnorm_kernel<<<MTOT, 128>>>(out, ln2_w, h2);

    // 6. gate = h2 @ gate_w^T -> fp32 plain
    gemm_f16<0,0><<<dim3(FF/128, MTOT/128), 256, GEMM_SMEM>>>(h2, wg, (const float*)nullptr, gate, MTOT, FF, D_MODEL);

    // 7. act = silu(gate) * (h2 @ up_w^T) -> half perm
    gemm_f16<2,1><<<dim3(FF/128, MTOT/128), 256, GEMM_SMEM>>>(h2, wu, gate, act, MTOT, FF, D_MODEL);

    // 8. out = x1 + act @ down_w^T -> d_out
    gemm_f16<1,0><<<dim3(D_MODEL/128, MTOT/128), 256, GEMM_SMEM>>>(act, wd, out, out, MTOT, D_MODEL, FF);
}

// round 9
// speedup vs baseline: 7.6383x; 1.0896x over previous
#include <cuda_runtime.h>
#include <cuda_fp16.h>
#include <math.h>
#include <stdint.h>

// Problem constants
#define D_MODEL 2048
#define SEQ     2048
#define BATCH   2
#define NHEAD   16
#define KVHEAD  4
#define HDIM    128
#define FF      5632
#define MTOT    (BATCH * SEQ)      // 4096
#define KD      (KVHEAD * HDIM)    // 512
#define QKV_N   3072
#define VOFF    2560

// ---------------------------------------------------------------------------
// Scratch (no cudaMalloc allowed)
// ---------------------------------------------------------------------------
__device__ __half g_h  [MTOT * (size_t)D_MODEL];   // rms1 out / attn out (half, pair-perm)
__device__ __half g_h2 [MTOT * (size_t)D_MODEL];   // rms2 out (half, pair-perm)
__device__ __half g_qkv[MTOT * (size_t)QKV_N];     // q|k plain half (v cols unused)
__device__ __half g_vT [(size_t)BATCH * KVHEAD * HDIM * SEQ];  // V transposed [b][g][d][seq]
__device__ __half g_gate[MTOT * (size_t)FF];       // gate (half, plain)
__device__ __half g_act[MTOT * (size_t)FF];        // swiglu (half, pair-perm)
// fp16 pair-permuted weights
__device__ __half w_qkvh[(size_t)QKV_N * D_MODEL];
__device__ __half w_oh  [(size_t)D_MODEL * D_MODEL];
__device__ __half w_gh  [(size_t)FF * D_MODEL];
__device__ __half w_uh  [(size_t)FF * D_MODEL];
__device__ __half w_dh  [(size_t)D_MODEL * FF];
__device__ float  b_qkv [QKV_N];

// Pair-permutation on 16-element K-groups (GEMM operands only)
__device__ __forceinline__ int ppos(int col) {
    const int j = (col >> 1) & 7;
    return (col & ~15) + 2 * ((j & 3) * 2 + (j >> 2));
}

#define MMA_F16(d, a, b)                                                    \
    asm volatile(                                                           \
        "mma.sync.aligned.m16n8k16.row.col.f32.f16.f16.f32 "                \
        "{%0,%1,%2,%3}, {%4,%5,%6,%7}, {%8,%9}, {%0,%1,%2,%3};"             \
        : "+f"(d[0]), "+f"(d[1]), "+f"(d[2]), "+f"(d[3])                    \
        : "r"(a[0]), "r"(a[1]), "r"(a[2]), "r"(a[3]), "r"(b[0]), "r"(b[1]))

__device__ __forceinline__ void cp_async16(void* dst, const void* src) {
    uint32_t s = (uint32_t)__cvta_generic_to_shared(dst);
    asm volatile("cp.async.cg.shared.global [%0], [%1], 16;\n" :: "r"(s), "l"(src));
}
__device__ __forceinline__ void cp_commit() {
    asm volatile("cp.async.commit_group;\n");
}
template<int N> __device__ __forceinline__ void cp_wait() {
    asm volatile("cp.async.wait_group %0;\n" :: "n"(N));
}

// ---------------------------------------------------------------------------
// cvt: fp32 weights -> fp16 pair-permuted; biases -> fp32 concat copy.
// ---------------------------------------------------------------------------
#define NSEG 10
struct CvtArgs {
    const float* s[NSEG];
    void* d[NSEG];
    int end[NSEG];
    int perm;
};

__global__ void __launch_bounds__(256) cvt_all_kernel(CvtArgs a, int totalg)
{
    const int i = blockIdx.x * 256 + threadIdx.x;
    if (i >= totalg) return;
    int j = 0;
    #pragma unroll
    for (int t = 0; t < NSEG - 1; ++t)
        if (i >= a.end[t]) j = t + 1;
    const int gi = i - (j ? a.end[j - 1] : 0);
    const float4* s = (const float4*)a.s[j] + gi * 4;
    float4 f0 = s[0], f1 = s[1], f2 = s[2], f3 = s[3];
    if ((a.perm >> j) & 1) {
        float n[16] = { f0.x,f0.y,f0.z,f0.w, f1.x,f1.y,f1.z,f1.w,
                        f2.x,f2.y,f2.z,f2.w, f3.x,f3.y,f3.z,f3.w };
        uint32_t w[8];
        #pragma unroll
        for (int p = 0; p < 8; ++p) {
            const int pp = (p & 3) * 2 + (p >> 2);
            __half2 h = __floats2half2_rn(n[2 * p], n[2 * p + 1]);
            w[pp] = *(uint32_t*)&h;
        }
        uint4* d = (uint4*)a.d[j] + gi * 2;
        uint4 o0; o0.x = w[0]; o0.y = w[1]; o0.z = w[2]; o0.w = w[3];
        uint4 o1; o1.x = w[4]; o1.y = w[5]; o1.z = w[6]; o1.w = w[7];
        d[0] = o0; d[1] = o1;
    } else {
        float4* d = (float4*)a.d[j] + gi * 4;
        d[0] = f0; d[1] = f1; d[2] = f2; d[3] = f3;
    }
}

// ---------------------------------------------------------------------------
// RMSNorm: fp32 in -> half pair-permuted out.
// ---------------------------------------------------------------------------
__global__ void __launch_bounds__(128) rmsnorm_kernel(
    const float* __restrict__ x, const float* __restrict__ w,
    __half* __restrict__ o)
{
    const int row = blockIdx.x;
    const float* xr = x + (size_t)row * D_MODEL;
    const int t = threadIdx.x;
    const int c0 = 16 * t;

    float4 f0 = *(const float4*)(xr + c0);
    float4 f1 = *(const float4*)(xr + c0 + 4);
    float4 f2 = *(const float4*)(xr + c0 + 8);
    float4 f3 = *(const float4*)(xr + c0 + 12);
    float n[16] = { f0.x,f0.y,f0.z,f0.w, f1.x,f1.y,f1.z,f1.w,
                    f2.x,f2.y,f2.z,f2.w, f3.x,f3.y,f3.z,f3.w };
    float ss = 0.f;
    #pragma unroll
    for (int i = 0; i < 16; ++i) ss += n[i] * n[i];
    #pragma unroll
    for (int off = 16; off; off >>= 1)
        ss += __shfl_xor_sync(0xffffffffu, ss, off);
    __shared__ float warp_s[4];
    if ((t & 31) == 0) warp_s[t >> 5] = ss;
    __syncthreads();
    float tot = warp_s[0] + warp_s[1] + warp_s[2] + warp_s[3];
    const float inv = rsqrtf(tot * (1.0f / D_MODEL) + 1e-6f);

    float4 w0 = *(const float4*)(w + c0);
    float4 w1 = *(const float4*)(w + c0 + 4);
    float4 w2 = *(const float4*)(w + c0 + 8);
    float4 w3 = *(const float4*)(w + c0 + 12);
    float wv[16] = { w0.x,w0.y,w0.z,w0.w, w1.x,w1.y,w1.z,w1.w,
                     w2.x,w2.y,w2.z,w2.w, w3.x,w3.y,w3.z,w3.w };
    uint32_t wd[8];
    #pragma unroll
    for (int p = 0; p < 8; ++p) {
        const int pp = (p & 3) * 2 + (p >> 2);
        __half2 h = __floats2half2_rn(n[2 * p] * inv * wv[2 * p],
                                      n[2 * p + 1] * inv * wv[2 * p + 1]);
        wd[pp] = *(uint32_t*)&h;
    }
    uint4* d = (uint4*)(o + (size_t)row * D_MODEL + c0);
    uint4 o0; o0.x = wd[0]; o0.y = wd[1]; o0.z = wd[2]; o0.w = wd[3];
    uint4 o1; o1.x = wd[4]; o1.y = wd[5]; o1.z = wd[6]; o1.w = wd[7];
    d[0] = o0; d[1] = o1;
}

// ---------------------------------------------------------------------------
// FP16 GEMM, 2-stage cp.async, LDS.64 fragments (pair-permuted operands).
//   EPI 0: +bias[col] (aux fp32 vec, may be null)
//   EPI 1: +aux[row,col] (fp32 matrix)
//   EPI 2: silu(aux[row,col]) * acc  (aux = half plain matrix)
//   OUT 0: fp32 plain  OUT 1: half pair-perm  OUT 2: half plain
//   OUT 3: qkv special — q/k cols plain half to Cv, v cols transposed to Cv2
// ---------------------------------------------------------------------------
#define GSTW 40
#define STAGE_W (2 * 128 * GSTW)
#define GEMM_SMEM (2 * STAGE_W * 4)

template<int EPI, int OUT>
__global__ void __launch_bounds__(256, 2) gemm_f16(
    const __half* __restrict__ A, const __half* __restrict__ W,
    const void* aux, void* __restrict__ Cv, void* __restrict__ Cv2,
    int M, int N, int K)
{
    extern __shared__ uint32_t smw[];
    const int tid  = threadIdx.x;
    const int warp = tid >> 5;
    const int lane = tid & 31;
    const int bm = blockIdx.y * 128;
    const int bn = blockIdx.x * 128;
    const int m_w = (warp >> 2) * 64;
    const int n_w = (warp & 3) * 32;
    const int lr4 = lane >> 2;
    const int lk  = lane & 3;

    const __half* Ab = A + (size_t)bm * K;
    const __half* Wb = W + (size_t)bn * K;

    float acc[4][4][4];
    #pragma unroll
    for (int mt = 0; mt < 4; ++mt)
        #pragma unroll
        for (int nt = 0; nt < 4; ++nt)
            #pragma unroll
            for (int r = 0; r < 4; ++r) acc[mt][nt][r] = 0.f;

    const int nk = K / 64;

    auto load_stage = [&](int st, int k0) {
        uint32_t* Aw = smw + st * STAGE_W;
        uint32_t* Bw = Aw + 128 * GSTW;
        #pragma unroll
        for (int i = 0; i < 4; ++i) {
            const int idx = tid + i * 256;
            const int row = idx >> 3;
            const int ch  = idx & 7;
            cp_async16(&Aw[row * GSTW + ch * 4], Ab + (size_t)row * K + k0 + ch * 8);
            cp_async16(&Bw[row * GSTW + ch * 4], Wb + (size_t)row * K + k0 + ch * 8);
        }
    };

    load_stage(0, 0);   cp_commit();
    if (nk > 1) load_stage(1, 64);
    cp_commit();

    for (int kt = 0; kt < nk; ++kt) {
        cp_wait<1>();
        __syncthreads();

        const uint32_t* As = smw + (kt & 1) * STAGE_W;
        const uint32_t* Bs = As + 128 * GSTW;
        #pragma unroll
        for (int kk = 0; kk < 4; ++kk) {
            const int k0 = kk * 8;
            uint32_t afr[4][4], bfr[4][2];
            #pragma unroll
            for (int mt = 0; mt < 4; ++mt) {
                const int r = m_w + mt * 16 + lr4;
                const uint2 lo = *(const uint2*)&As[r * GSTW + k0 + 2 * lk];
                const uint2 hi = *(const uint2*)&As[(r + 8) * GSTW + k0 + 2 * lk];
                afr[mt][0] = lo.x; afr[mt][2] = lo.y;
                afr[mt][1] = hi.x; afr[mt][3] = hi.y;
            }
            #pragma unroll
            for (int nt = 0; nt < 4; ++nt) {
                const int rn = n_w + nt * 8 + lr4;
                const uint2 bb = *(const uint2*)&Bs[rn * GSTW + k0 + 2 * lk];
                bfr[nt][0] = bb.x; bfr[nt][1] = bb.y;
            }
            #pragma unroll
            for (int mt = 0; mt < 4; ++mt)
                #pragma unroll
                for (int nt = 0; nt < 4; ++nt)
                    MMA_F16(acc[mt][nt], afr[mt], bfr[nt]);
        }
        __syncthreads();
        if (kt + 2 < nk) load_stage(kt & 1, (kt + 2) * 64);
        cp_commit();
    }

    // ---- epilogue ----
    #pragma unroll
    for (int mt = 0; mt < 4; ++mt) {
        #pragma unroll
        for (int half = 0; half < 2; ++half) {
            const int row = bm + m_w + mt * 16 + lr4 + half * 8;
            const size_t base = (size_t)row * N;
            #pragma unroll
            for (int nt = 0; nt < 4; ++nt) {
                const int col = bn + n_w + nt * 8 + 2 * lk;
                float v0 = acc[mt][nt][half * 2 + 0];
                float v1 = acc[mt][nt][half * 2 + 1];
                if (EPI == 0) {
                    if (aux) {
                        const float* bz = (const float*)aux;
                        v0 += bz[col]; v1 += bz[col + 1];
                    }
                } else if (EPI == 1) {
                    const float* r = (const float*)aux;
                    v0 += r[base + col]; v1 += r[base + col + 1];
                } else {
                    const __half2 gh = *(const __half2*)((const __half*)aux + base + col);
                    const float ga = __low2float(gh), gb = __high2float(gh);
                    v0 *= ga / (1.0f + __expf(-ga));
                    v1 *= gb / (1.0f + __expf(-gb));
                }
                if (OUT == 0) {
                    float2 r; r.x = v0; r.y = v1;
                    *(float2*)((float*)Cv + base + col) = r;
                } else if (OUT == 1) {
                    *(__half2*)((__half*)Cv + base + ppos(col)) = __floats2half2_rn(v0, v1);
                } else if (OUT == 2) {
                    *(__half2*)((__half*)Cv + base + col) = __floats2half2_rn(v0, v1);
                } else {
                    if (col < VOFF) {
                        *(__half2*)((__half*)Cv + base + col) = __floats2half2_rn(v0, v1);
                    } else {
                        const int c = col - VOFF;
                        const int gidx = c >> 7, d = c & 127;
                        const int bb = row >> 11, sp = row & (SEQ - 1);
                        __half* vt = (__half*)Cv2 +
                            ((size_t)(bb * KVHEAD + gidx) * HDIM + d) * SEQ + sp;
                        vt[0]   = __float2half_rn(v0);
                        vt[SEQ] = __float2half_rn(v1);
                    }
                }
            }
        }
    }
}

// ---------------------------------------------------------------------------
// Flash attention, full fp16 MMA (m16n8k16), half K/V, V pre-transposed.
// ---------------------------------------------------------------------------
#define FQT 128
#define FKT 64
#define KSTH 136                         // halves; 68 words/row (== 4 mod 32)
#define VSTH 72                          // halves; 36 words/row
#define PSTH 72
#define KV_STAGE_H (FKT * KSTH + HDIM * VSTH)            // 17920 halves
#define FLASH_SMEM ((2 * KV_STAGE_H + FQT * PSTH) * 2)   // 90112 bytes

__global__ void __launch_bounds__(256) flash_tc_kernel(
    const __half* __restrict__ qkv, const __half* __restrict__ vT,
    __half* __restrict__ Ob)
{
    extern __shared__ __half fsh[];
    __half* S0 = fsh;
    __half* S1 = fsh + KV_STAGE_H;
    __half* Ps = fsh + 2 * KV_STAGE_H;

    const int bx   = (SEQ / FQT - 1) - blockIdx.x;   // heavy tiles first
    const int hh   = blockIdx.y;
    const int b    = blockIdx.z;
    const int g    = hh & (KVHEAD - 1);
    const int tid  = threadIdx.x;
    const int warp = tid >> 5;
    const int lane = tid & 31;
    const int lr   = lane >> 2;
    const int lq   = lane & 3;
    const int mb   = warp * 16;
    const int qbase = bx * FQT;
    const float scale = 0.08838834764831845f;

    // ---- stage Q (plain half) into S0, extract fp16 fragments ----
    const __half* qp = qkv + ((size_t)(b * SEQ + qbase)) * QKV_N + hh * HDIM;
    #pragma unroll
    for (int it = 0; it < 8; ++it) {
        const int idx = tid + it * 256;
        const int row = idx >> 4;
        const int ch  = idx & 15;
        *(uint4*)&S0[row * KSTH + ch * 8] =
            *(const uint4*)(qp + (size_t)row * QKV_N + ch * 8);
    }
    __syncthreads();
    uint32_t qf[8][4];
    #pragma unroll
    for (int kk = 0; kk < 8; ++kk) {
        const int k0 = kk * 16 + 2 * lq;
        qf[kk][0] = *(const uint32_t*)&S0[(mb + lr)     * KSTH + k0];
        qf[kk][1] = *(const uint32_t*)&S0[(mb + lr + 8) * KSTH + k0];
        qf[kk][2] = *(const uint32_t*)&S0[(mb + lr)     * KSTH + k0 + 8];
        qf[kk][3] = *(const uint32_t*)&S0[(mb + lr + 8) * KSTH + k0 + 8];
    }
    __syncthreads();

    const int nkt = 2 * (bx + 1);

    auto load_kv = [&](__half* St, int ktb) {
        __half* Kd = St;
        __half* Vd = St + FKT * KSTH;
        const __half* kp = qkv + ((size_t)(b * SEQ + ktb)) * QKV_N + D_MODEL + g * HDIM;
        const __half* vp = vT + ((size_t)(b * KVHEAD + g) * HDIM) * SEQ + ktb;
        #pragma unroll
        for (int it = 0; it < 4; ++it) {
            const int idx = tid + it * 256;
            { // K: 64 rows x 128 halves
                const int row = idx >> 4, ch = idx & 15;
                cp_async16(&Kd[row * KSTH + ch * 8], kp + (size_t)row * QKV_N + ch * 8);
            }
            { // Vt: 128 rows x 64 halves
                const int row = idx >> 3, ch = idx & 7;
                cp_async16(&Vd[row * VSTH + ch * 8], vp + (size_t)row * SEQ + ch * 8);
            }
        }
    };

    load_kv(S0, 0);
    cp_commit();
    if (nkt > 1) load_kv(S1, FKT);
    cp_commit();

    float o[16][4];
    #pragma unroll
    for (int nt = 0; nt < 16; ++nt)
        o[nt][0] = o[nt][1] = o[nt][2] = o[nt][3] = 0.f;
    float m0 = -1e30f, m1 = -1e30f, l0 = 0.f, l1 = 0.f;
    const int r0g = qbase + mb + lr;
    const int r1g = r0g + 8;

    for (int kt = 0; kt < nkt; ++kt) {
        cp_wait<1>();
        __syncthreads();
        const __half* St = (kt & 1) ? S1 : S0;
        const __half* Ks = St;
        const __half* Vs = St + FKT * KSTH;
        const int ktb = kt * FKT;

        // ---- S = Q K^T (16 x 64 per warp), fp16 MMA ----
        float s[8][4];
        #pragma unroll
        for (int nt = 0; nt < 8; ++nt)
            s[nt][0] = s[nt][1] = s[nt][2] = s[nt][3] = 0.f;
        #pragma unroll
        for (int kk = 0; kk < 8; ++kk) {
            const int k0 = kk * 16 + 2 * lq;
            #pragma unroll
            for (int nt = 0; nt < 8; ++nt) {
                uint32_t bfr[2];
                bfr[0] = *(const uint32_t*)&Ks[(nt * 8 + lr) * KSTH + k0];
                bfr[1] = *(const uint32_t*)&Ks[(nt * 8 + lr) * KSTH + k0 + 8];
                MMA_F16(s[nt], qf[kk], bfr);
            }
        }

        // ---- scale + causal mask + online softmax ----
        float mx0 = -1e30f, mx1 = -1e30f;
        #pragma unroll
        for (int nt = 0; nt < 8; ++nt) {
            const int c = ktb + nt * 8 + 2 * lq;
            s[nt][0] = (c     <= r0g) ? s[nt][0] * scale : -1e30f;
            s[nt][1] = (c + 1 <= r0g) ? s[nt][1] * scale : -1e30f;
            s[nt][2] = (c     <= r1g) ? s[nt][2] * scale : -1e30f;
            s[nt][3] = (c + 1 <= r1g) ? s[nt][3] * scale : -1e30f;
            mx0 = fmaxf(mx0, fmaxf(s[nt][0], s[nt][1]));
            mx1 = fmaxf(mx1, fmaxf(s[nt][2], s[nt][3]));
        }
        mx0 = fmaxf(mx0, __shfl_xor_sync(0xffffffffu, mx0, 1));
        mx0 = fmaxf(mx0, __shfl_xor_sync(0xffffffffu, mx0, 2));
        mx1 = fmaxf(mx1, __shfl_xor_sync(0xffffffffu, mx1, 1));
        mx1 = fmaxf(mx1, __shfl_xor_sync(0xffffffffu, mx1, 2));
        const float mn0 = fmaxf(m0, mx0), mn1 = fmaxf(m1, mx1);
        const float al0 = __expf(m0 - mn0), al1 = __expf(m1 - mn1);
        m0 = mn0; m1 = mn1;

        float ps0 = 0.f, ps1 = 0.f;
        #pragma unroll
        for (int nt = 0; nt < 8; ++nt) {
            const float p0 = __expf(s[nt][0] - mn0);
            const float p1 = __expf(s[nt][1] - mn0);
            const float p2 = __expf(s[nt][2] - mn1);
            const float p3 = __expf(s[nt][3] - mn1);
            ps0 += p0 + p1; ps1 += p2 + p3;
            *(__half2*)&Ps[(mb + lr)     * PSTH + nt * 8 + 2 * lq] = __floats2half2_rn(p0, p1);
            *(__half2*)&Ps[(mb + lr + 8) * PSTH + nt * 8 + 2 * lq] = __floats2half2_rn(p2, p3);
        }
        ps0 += __shfl_xor_sync(0xffffffffu, ps0, 1);
        ps0 += __shfl_xor_sync(0xffffffffu, ps0, 2);
        ps1 += __shfl_xor_sync(0xffffffffu, ps1, 1);
        ps1 += __shfl_xor_sync(0xffffffffu, ps1, 2);
        l0 = l0 * al0 + ps0;
        l1 = l1 * al1 + ps1;

        #pragma unroll
        for (int nt = 0; nt < 16; ++nt) {
            o[nt][0] *= al0; o[nt][1] *= al0;
            o[nt][2] *= al1; o[nt][3] *= al1;
        }
        __syncwarp();   // P rows are warp-private

        // ---- O += P V (fp16 MMA, K=64 -> 4 k16 chunks) ----
        #pragma unroll
        for (int kk = 0; kk < 4; ++kk) {
            const int k0 = kk * 16 + 2 * lq;
            uint32_t a[4];
            a[0] = *(const uint32_t*)&Ps[(mb + lr)     * PSTH + k0];
            a[1] = *(const uint32_t*)&Ps[(mb + lr + 8) * PSTH + k0];
            a[2] = *(const uint32_t*)&Ps[(mb + lr)     * PSTH + k0 + 8];
            a[3] = *(const uint32_t*)&Ps[(mb + lr + 8) * PSTH + k0 + 8];
            #pragma unroll
            for (int nt = 0; nt < 16; ++nt) {
                uint32_t bfr[2];
                bfr[0] = *(const uint32_t*)&Vs[(nt * 8 + lr) * VSTH + k0];
                bfr[1] = *(const uint32_t*)&Vs[(nt * 8 + lr) * VSTH + k0 + 8];
                MMA_F16(o[nt], a, bfr);
            }
        }
        __syncthreads();

        const int nx = kt + 2;
        if (nx < nkt) load_kv((nx & 1) ? S1 : S0, nx * FKT);
        cp_commit();
    }

    // write O: half pair-perm (feeds o-proj GEMM)
    const float i0 = 1.0f / l0, i1 = 1.0f / l1;
    __half* op = Ob + ((size_t)(b * SEQ + qbase + mb)) * D_MODEL;
    #pragma unroll
    for (int nt = 0; nt < 16; ++nt) {
        const int label = hh * HDIM + nt * 8 + 2 * lq;
        const int pos = ppos(label);
        *(__half2*)(op + (size_t)lr * D_MODEL + pos) =
            __floats2half2_rn(o[nt][0] * i0, o[nt][1] * i0);
        *(__half2*)(op + (size_t)(lr + 8) * D_MODEL + pos) =
            __floats2half2_rn(o[nt][2] * i1, o[nt][3] * i1);
    }
}

// ---------------------------------------------------------------------------
// Launch sequence
// ---------------------------------------------------------------------------
extern "C" void kernel_launch(void* const* d_in, const int* in_sizes, int n_in,
                              void* d_out, int out_size)
{
    const float* x      = (const float*)d_in[0];
    const float* ln1_w  = (const float*)d_in[1];
    const float* q_w    = (const float*)d_in[2];
    const float* q_b    = (const float*)d_in[3];
    const float* k_w    = (const float*)d_in[4];
    const float* k_b    = (const float*)d_in[5];
    const float* v_w    = (const float*)d_in[6];
    const float* v_b    = (const float*)d_in[7];
    const float* o_w    = (const float*)d_in[8];
    const float* ln2_w  = (const float*)d_in[9];
    const float* gate_w = (const float*)d_in[10];
    const float* up_w   = (const float*)d_in[11];
    const float* down_w = (const float*)d_in[12];
    float* out = (float*)d_out;

    __half *h, *h2, *act, *qkv, *vT, *gate;
    float *bq;
    __half *wqkv, *wo, *wg, *wu, *wd;
    cudaGetSymbolAddress((void**)&h,    g_h);
    cudaGetSymbolAddress((void**)&h2,   g_h2);
    cudaGetSymbolAddress((void**)&qkv,  g_qkv);
    cudaGetSymbolAddress((void**)&vT,   g_vT);
    cudaGetSymbolAddress((void**)&gate, g_gate);
    cudaGetSymbolAddress((void**)&act,  g_act);
    cudaGetSymbolAddress((void**)&wqkv, w_qkvh);
    cudaGetSymbolAddress((void**)&wo,   w_oh);
    cudaGetSymbolAddress((void**)&wg,   w_gh);
    cudaGetSymbolAddress((void**)&wu,   w_uh);
    cudaGetSymbolAddress((void**)&wd,   w_dh);
    cudaGetSymbolAddress((void**)&bq,   b_qkv);

    cudaFuncSetAttribute(gemm_f16<0,3>, cudaFuncAttributeMaxDynamicSharedMemorySize, GEMM_SMEM);
    cudaFuncSetAttribute(gemm_f16<1,0>, cudaFuncAttributeMaxDynamicSharedMemorySize, GEMM_SMEM);
    cudaFuncSetAttribute(gemm_f16<0,2>, cudaFuncAttributeMaxDynamicSharedMemorySize, GEMM_SMEM);
    cudaFuncSetAttribute(gemm_f16<2,1>, cudaFuncAttributeMaxDynamicSharedMemorySize, GEMM_SMEM);
    cudaFuncSetAttribute(flash_tc_kernel, cudaFuncAttributeMaxDynamicSharedMemorySize, FLASH_SMEM);

    // 0. convert weights (pair-perm fp16) + concat biases
    {
        CvtArgs a;
        const float* srcs[NSEG] = { q_w, k_w, v_w, o_w, gate_w, up_w, down_w,
                                    q_b, k_b, v_b };
        void* dsts[NSEG] = { (void*)wqkv,
                             (void*)(wqkv + (size_t)D_MODEL * D_MODEL),
                             (void*)(wqkv + (size_t)VOFF * D_MODEL),
                             (void*)wo, (void*)wg, (void*)wu, (void*)wd,
                             (void*)bq, (void*)(bq + D_MODEL), (void*)(bq + VOFF) };
        const long long n[NSEG] = {
            (long long)D_MODEL*D_MODEL, (long long)KD*D_MODEL, (long long)KD*D_MODEL,
            (long long)D_MODEL*D_MODEL, (long long)FF*D_MODEL, (long long)FF*D_MODEL,
            (long long)D_MODEL*FF, D_MODEL, KD, KD };
        int accg = 0;
        for (int i = 0; i < NSEG; ++i) {
            a.s[i] = srcs[i]; a.d[i] = dsts[i];
            accg += (int)(n[i] / 16); a.end[i] = accg;
        }
        a.perm = 0x7F;
        cvt_all_kernel<<<(accg + 255) / 256, 256>>>(a, accg);
    }

    // 1. h = rmsnorm(x, ln1)  [half, perm]
    rmsnorm_kernel<<<MTOT, 128>>>(x, ln1_w, h);

    // 2. fused qkv projection: q/k plain half, v transposed
    gemm_f16<0,3><<<dim3(QKV_N/128, MTOT/128), 256, GEMM_SMEM>>>(
        h, wqkv, bq, qkv, vT, MTOT, QKV_N, D_MODEL);

    // 3. flash attention (fp16) -> g_h
    flash_tc_kernel<<<dim3(SEQ/FQT, NHEAD, BATCH), 256, FLASH_SMEM>>>(qkv, vT, h);

    // 4. x1 = x + attn @ o_w^T -> d_out
    gemm_f16<1,0><<<dim3(D_MODEL/128, MTOT/128), 256, GEMM_SMEM>>>(
        h, wo, x, out, nullptr, MTOT, D_MODEL, D_MODEL);

    // 5. h2 = rmsnorm(x1, ln2)  [half, perm]
    rmsnorm_kernel<<<MTOT, 128>>>(out, ln2_w, h2);

    // 6. gate = h2 @ gate_w^T -> half plain
    gemm_f16<0,2><<<dim3(FF/128, MTOT/128), 256, GEMM_SMEM>>>(
        h2, wg, nullptr, gate, nullptr, MTOT, FF, D_MODEL);

    // 7. act = silu(gate) * (h2 @ up_w^T) -> half perm
    gemm_f16<2,1><<<dim3(FF/128, MTOT/128), 256, GEMM_SMEM>>>(
        h2, wu, gate, act, nullptr, MTOT, FF, D_MODEL);

    // 8. out = x1 + act @ down_w^T -> d_out
    gemm_f16<1,0><<<dim3(D_MODEL/128, MTOT/128), 256, GEMM_SMEM>>>(
        act, wd, out, out, nullptr, MTOT, D_MODEL, FF);
}